// round 1
// baseline (speedup 1.0000x reference)
#include <cuda_runtime.h>
#include <cuda_bf16.h>
#include <math.h>

// ---------------------------------------------------------------------------
// Problem constants
// ---------------------------------------------------------------------------
namespace {
constexpr int cB   = 2;
constexpr int cS   = 2048;
constexpr int cHID = 2048;
constexpr int cNH  = 16;
constexpr int cNKV = 8;
constexpr int cHD  = 128;
constexpr float cEPS   = 1e-6f;
constexpr float cSCALE = 0.08838834764831845f;  // 128^-0.5
}

// Scratch (device globals -- no runtime allocation allowed)
__device__ float g_q  [(size_t)cB * cS * cNH  * cHD];   // (b, s, h, d)
__device__ float g_k  [(size_t)cB * cS * cNKV * cHD];   // (b, s, kvh, d)
__device__ float g_v  [(size_t)cB * cS * cNKV * cHD];   // (b, s, kvh, d)
__device__ float g_att[(size_t)cB * cS * cNH  * cHD];   // (b, s, h*d) pre-Wo

// ---------------------------------------------------------------------------
// SGEMM: C[M,N] = A[M,K] @ W[K,N], all row-major fp32.
// 128x128 block tile, BK=16, 256 threads, 8x8 per thread.
// ---------------------------------------------------------------------------
__global__ __launch_bounds__(256) void sgemm_kernel(
    const float* __restrict__ A, const float* __restrict__ W,
    float* __restrict__ C, int M, int N, int K)
{
    __shared__ float As[16 * 132];   // [k][m], padded stride 132
    __shared__ float Bs[16 * 128];   // [k][n]

    const int tid = threadIdx.x;
    const int m0 = blockIdx.y * 128;
    const int n0 = blockIdx.x * 128;
    const int ty = tid >> 4;         // 0..15
    const int tx = tid & 15;         // 0..15

    float acc[8][8];
#pragma unroll
    for (int i = 0; i < 8; i++)
#pragma unroll
        for (int j = 0; j < 8; j++) acc[i][j] = 0.f;

    for (int k0 = 0; k0 < K; k0 += 16) {
        // A tile: 128 rows x 16 cols -> transposed store into As[k][m]
#pragma unroll
        for (int i = 0; i < 2; i++) {
            int idx = tid + i * 256;          // 0..511 float4 slots
            int row = idx >> 2;               // 0..127
            int kq  = (idx & 3) << 2;         // 0,4,8,12
            float4 f = *(const float4*)(A + (size_t)(m0 + row) * K + k0 + kq);
            As[(kq + 0) * 132 + row] = f.x;
            As[(kq + 1) * 132 + row] = f.y;
            As[(kq + 2) * 132 + row] = f.z;
            As[(kq + 3) * 132 + row] = f.w;
        }
        // B tile: 16 rows x 128 cols -> direct store
#pragma unroll
        for (int i = 0; i < 2; i++) {
            int idx = tid + i * 256;
            int r = idx >> 5;                 // 0..15
            int c = (idx & 31) << 2;          // 0..124
            *(float4*)&Bs[r * 128 + c] =
                *(const float4*)(W + (size_t)(k0 + r) * N + n0 + c);
        }
        __syncthreads();

#pragma unroll
        for (int kk = 0; kk < 16; kk++) {
            float a[8], b[8];
            *(float4*)&a[0] = *(float4*)&As[kk * 132 + ty * 8];
            *(float4*)&a[4] = *(float4*)&As[kk * 132 + ty * 8 + 4];
            *(float4*)&b[0] = *(float4*)&Bs[kk * 128 + tx * 8];
            *(float4*)&b[4] = *(float4*)&Bs[kk * 128 + tx * 8 + 4];
#pragma unroll
            for (int i = 0; i < 8; i++)
#pragma unroll
                for (int j = 0; j < 8; j++)
                    acc[i][j] += a[i] * b[j];
        }
        __syncthreads();
    }

#pragma unroll
    for (int i = 0; i < 8; i++) {
        float* crow = C + (size_t)(m0 + ty * 8 + i) * N + n0 + tx * 8;
        *(float4*)(crow)     = make_float4(acc[i][0], acc[i][1], acc[i][2], acc[i][3]);
        *(float4*)(crow + 4) = make_float4(acc[i][4], acc[i][5], acc[i][6], acc[i][7]);
    }
}

// ---------------------------------------------------------------------------
// Per-head RMSNorm + RoPE for Q and K (in place on g_q / g_k).
// One block (128 threads) per (b, s, head-slot).
// ---------------------------------------------------------------------------
__global__ __launch_bounds__(128) void norm_rope_kernel(
    const float* __restrict__ cosp, const float* __restrict__ sinp,
    const float* __restrict__ qw,   const float* __restrict__ kw)
{
    const int slot = blockIdx.x % (cNH + cNKV);
    const int bs   = blockIdx.x / (cNH + cNKV);   // b*S + s
    const int d    = threadIdx.x;                 // 0..127

    float* ptr;
    const float* w;
    if (slot < cNH) { ptr = g_q + ((size_t)bs * cNH  + slot)        * cHD; w = qw; }
    else            { ptr = g_k + ((size_t)bs * cNKV + (slot - cNH)) * cHD; w = kw; }

    float x = ptr[d];
    float v = x * x;
#pragma unroll
    for (int o = 16; o; o >>= 1) v += __shfl_xor_sync(0xffffffffu, v, o);

    __shared__ float wsum[4];
    if ((d & 31) == 0) wsum[d >> 5] = v;
    __syncthreads();
    float var = (wsum[0] + wsum[1] + wsum[2] + wsum[3]) * (1.f / cHD);
    float rs  = rsqrtf(var + cEPS);
    float xn  = x * rs * w[d];

    __shared__ float buf[cHD];
    buf[d] = xn;
    __syncthreads();
    float other = (d < cHD / 2) ? -buf[d + cHD / 2] : buf[d - cHD / 2];

    float cv = cosp[(size_t)bs * cHD + d];
    float sv = sinp[(size_t)bs * cHD + d];
    ptr[d] = xn * cv + other * sv;
}

// ---------------------------------------------------------------------------
// Attention helpers
// ---------------------------------------------------------------------------
// Load a 64-row x 128-col fp32 tile transposed into dst[d*64 + row].
__device__ __forceinline__ void load_tile_T(float* dst, const float* src,
                                            int srcStride, int tid)
{
#pragma unroll
    for (int i = 0; i < 8; i++) {
        int idx = tid + (i << 8);        // 0..2047 float4 slots
        int row = idx & 63;
        int c4  = idx >> 6;              // 0..31
        float4 f = *(const float4*)(src + (size_t)row * srcStride + (c4 << 2));
        dst[(c4 * 4 + 0) * 64 + row] = f.x;
        dst[(c4 * 4 + 1) * 64 + row] = f.y;
        dst[(c4 * 4 + 2) * 64 + row] = f.z;
        dst[(c4 * 4 + 3) * 64 + row] = f.w;
    }
}

// 64x64 score tile: each thread computes 2 rows x 8 cols.
__device__ __forceinline__ void compute_scores(const float* Qs, const float* Ks,
                                               int r0, int c0, float (&acc)[2][8])
{
#pragma unroll
    for (int i = 0; i < 2; i++)
#pragma unroll
        for (int j = 0; j < 8; j++) acc[i][j] = 0.f;

#pragma unroll 4
    for (int d = 0; d < cHD; d++) {
        float2 qv  = *(const float2*)&Qs[d * 64 + r0];
        float4 k0v = *(const float4*)&Ks[d * 64 + c0];
        float4 k1v = *(const float4*)&Ks[d * 64 + c0 + 4];
        float kv[8] = {k0v.x, k0v.y, k0v.z, k0v.w, k1v.x, k1v.y, k1v.z, k1v.w};
#pragma unroll
        for (int j = 0; j < 8; j++) {
            acc[0][j] += qv.x * kv[j];
            acc[1][j] += qv.y * kv[j];
        }
    }
}

// ---------------------------------------------------------------------------
// Two-pass causal attention.
// Grid: (S/64, B*NH). Block: 256 threads, BM=BN=64.
// Pass 1: online row max m / sum l over valid keys.
// Pass 2: normalized weights -> gmem (attn_weights) + PV accumulation.
// ---------------------------------------------------------------------------
__global__ __launch_bounds__(256) void attn_kernel(float* __restrict__ wout,
                                                   int write_w)
{
    extern __shared__ float sm[];
    float* Qs = sm;                  // [128][64]
    float* Ks = Qs + 128 * 64;       // [128][64]
    float* Vs = Ks + 128 * 64;       // [64][128]
    float* Ws = Vs + 64 * 128;       // [64][65]

    const int tid = threadIdx.x;
    const int ty  = tid >> 3;        // 0..31
    const int tx  = tid & 7;         // 0..7
    const int bh  = blockIdx.y;
    const int b   = bh >> 4;
    const int h   = bh & 15;
    const int kvh = h >> 1;          // GROUPS = 2
    const int q0  = blockIdx.x << 6;
    const int r0  = ty * 2;
    const int c0  = tx * 8;

    const float* qb  = g_q + ((size_t)(b * cS + q0) * cNH + h) * cHD;
    const float* kbb = g_k + ((size_t)(b * cS) * cNKV + kvh) * cHD;
    const float* vbb = g_v + ((size_t)(b * cS) * cNKV + kvh) * cHD;

    // Q tile resident for the whole block
    load_tile_T(Qs, qb, cNH * cHD, tid);

    const int ktd = q0 >> 6;                 // diagonal key tile index
    float mr[2] = {-1e30f, -1e30f};
    float lr[2] = {0.f, 0.f};

    // ---------------- pass 1: row max / sum ----------------
    for (int kt = 0; kt <= ktd; kt++) {
        __syncthreads();
        load_tile_T(Ks, kbb + (size_t)(kt << 6) * (cNKV * cHD), cNKV * cHD, tid);
        __syncthreads();

        float acc[2][8];
        compute_scores(Qs, Ks, r0, c0, acc);

        const bool diag = (kt == ktd);
#pragma unroll
        for (int i = 0; i < 2; i++) {
#pragma unroll
            for (int j = 0; j < 8; j++) {
                float s = acc[i][j] * cSCALE;
                if (diag && (c0 + j > r0 + i)) s = -1e30f;
                acc[i][j] = s;
            }
            float tm = acc[i][0];
#pragma unroll
            for (int j = 1; j < 8; j++) tm = fmaxf(tm, acc[i][j]);
#pragma unroll
            for (int o = 1; o < 8; o <<= 1)
                tm = fmaxf(tm, __shfl_xor_sync(0xffffffffu, tm, o));
            float mn = fmaxf(mr[i], tm);
            float p = 0.f;
#pragma unroll
            for (int j = 0; j < 8; j++) p += __expf(acc[i][j] - mn);
#pragma unroll
            for (int o = 1; o < 8; o <<= 1)
                p += __shfl_xor_sync(0xffffffffu, p, o);
            lr[i] = lr[i] * __expf(mr[i] - mn) + p;
            mr[i] = mn;
        }
    }

    float invl[2];
#pragma unroll
    for (int i = 0; i < 2; i++) invl[i] = 1.f / lr[i];

    float acco[2][16];
#pragma unroll
    for (int i = 0; i < 2; i++)
#pragma unroll
        for (int j = 0; j < 16; j++) acco[i][j] = 0.f;

    const size_t wbase = ((size_t)(b * cNH + h) * cS + q0) * cS;

    // ---------------- pass 2: weights + PV ----------------
    for (int kt = 0; kt <= ktd; kt++) {
        __syncthreads();
        load_tile_T(Ks, kbb + (size_t)(kt << 6) * (cNKV * cHD), cNKV * cHD, tid);
        // V tile, natural layout Vs[k][d]
#pragma unroll
        for (int i = 0; i < 8; i++) {
            int idx = tid + (i << 8);
            int row = idx >> 5;               // 0..63
            int c4  = idx & 31;               // 0..31
            const float* vb = vbb + (size_t)((kt << 6) + row) * (cNKV * cHD);
            *(float4*)&Vs[row * 128 + (c4 << 2)] = *(const float4*)(vb + (c4 << 2));
        }
        __syncthreads();

        float acc[2][8];
        compute_scores(Qs, Ks, r0, c0, acc);

        const bool diag = (kt == ktd);
        float w[2][8];
#pragma unroll
        for (int i = 0; i < 2; i++)
#pragma unroll
            for (int j = 0; j < 8; j++) {
                float s  = acc[i][j] * cSCALE;
                float wv = __expf(s - mr[i]) * invl[i];
                if (diag && (c0 + j > r0 + i)) wv = 0.f;
                w[i][j] = wv;
            }

        if (write_w) {
#pragma unroll
            for (int i = 0; i < 2; i++) {
                float* wp = wout + wbase + (size_t)(r0 + i) * cS + (kt << 6) + c0;
                *(float4*)(wp)     = make_float4(w[i][0], w[i][1], w[i][2], w[i][3]);
                *(float4*)(wp + 4) = make_float4(w[i][4], w[i][5], w[i][6], w[i][7]);
            }
        }

        // Ws[r][c], stride 65
#pragma unroll
        for (int i = 0; i < 2; i++)
#pragma unroll
            for (int j = 0; j < 8; j++)
                Ws[(r0 + i) * 65 + c0 + j] = w[i][j];
        __syncthreads();

        // PV: O[r][dc] += sum_kk W[r][kk] * V[kk][dc]; 16 cols per thread
        const int cc = tx * 16;
#pragma unroll 2
        for (int kk = 0; kk < 64; kk++) {
            float wa = Ws[r0 * 65 + kk];
            float wb = Ws[(r0 + 1) * 65 + kk];
            float4 v0 = *(const float4*)&Vs[kk * 128 + cc];
            float4 v1 = *(const float4*)&Vs[kk * 128 + cc + 4];
            float4 v2 = *(const float4*)&Vs[kk * 128 + cc + 8];
            float4 v3 = *(const float4*)&Vs[kk * 128 + cc + 12];
            float vv[16] = {v0.x, v0.y, v0.z, v0.w, v1.x, v1.y, v1.z, v1.w,
                            v2.x, v2.y, v2.z, v2.w, v3.x, v3.y, v3.z, v3.w};
#pragma unroll
            for (int j = 0; j < 16; j++) {
                acco[0][j] += wa * vv[j];
                acco[1][j] += wb * vv[j];
            }
        }
    }

    // Zero-fill weights beyond the causal frontier
    if (write_w) {
        int z0 = q0 + 64;
        if (z0 < cS) {
            int zlen4 = (cS - z0) >> 2;
            float4 z4 = make_float4(0.f, 0.f, 0.f, 0.f);
            int tot = 64 * zlen4;
            for (int t = tid; t < tot; t += 256) {
                int r  = t / zlen4;
                int c4 = t - r * zlen4;
                *(float4*)(wout + wbase + (size_t)r * cS + z0 + (c4 << 2)) = z4;
            }
        }
    }

    // Write O (already normalized) into g_att (b, s, h*d layout)
#pragma unroll
    for (int i = 0; i < 2; i++) {
        float* ob = g_att + ((size_t)(b * cS + q0 + r0 + i) * cNH + h) * cHD + tx * 16;
        *(float4*)(ob)      = make_float4(acco[i][0],  acco[i][1],  acco[i][2],  acco[i][3]);
        *(float4*)(ob + 4)  = make_float4(acco[i][4],  acco[i][5],  acco[i][6],  acco[i][7]);
        *(float4*)(ob + 8)  = make_float4(acco[i][8],  acco[i][9],  acco[i][10], acco[i][11]);
        *(float4*)(ob + 12) = make_float4(acco[i][12], acco[i][13], acco[i][14], acco[i][15]);
    }
}

// ---------------------------------------------------------------------------
// Launch
// ---------------------------------------------------------------------------
extern "C" void kernel_launch(void* const* d_in, const int* in_sizes, int n_in,
                              void* d_out, int out_size)
{
    const float* hidden = (const float*)d_in[0];
    const float* cosp   = (const float*)d_in[1];
    const float* sinp   = (const float*)d_in[2];
    // d_in[3] = attention_mask (pure causal -1e9; handled analytically)
    const float* wq  = (const float*)d_in[4];
    const float* wk  = (const float*)d_in[5];
    const float* wv  = (const float*)d_in[6];
    const float* wo  = (const float*)d_in[7];
    const float* qnw = (const float*)d_in[8];
    const float* knw = (const float*)d_in[9];

    float* out = (float*)d_out;
    const size_t n_attn = (size_t)cB * cS * cHID;            // 8,388,608
    const size_t n_w    = (size_t)cB * cNH * cS * cS;        // 134,217,728
    const int write_w   = ((size_t)out_size >= n_attn + n_w) ? 1 : 0;
    float* weights = out + n_attn;

    float *pq, *pk, *pv, *pa;
    cudaGetSymbolAddress((void**)&pq, g_q);
    cudaGetSymbolAddress((void**)&pk, g_k);
    cudaGetSymbolAddress((void**)&pv, g_v);
    cudaGetSymbolAddress((void**)&pa, g_att);

    const int M = cB * cS;  // 4096

    // QKV projections
    sgemm_kernel<<<dim3((cNH  * cHD) / 128, M / 128), 256>>>(hidden, wq, pq, M, cNH  * cHD, cHID);
    sgemm_kernel<<<dim3((cNKV * cHD) / 128, M / 128), 256>>>(hidden, wk, pk, M, cNKV * cHD, cHID);
    sgemm_kernel<<<dim3((cNKV * cHD) / 128, M / 128), 256>>>(hidden, wv, pv, M, cNKV * cHD, cHID);

    // RMSNorm + RoPE on q, k heads
    norm_rope_kernel<<<cB * cS * (cNH + cNKV), 128>>>(cosp, sinp, qnw, knw);

    // Attention (weights + context)
    const size_t smem = (size_t)(128 * 64 + 128 * 64 + 64 * 128 + 64 * 65) * sizeof(float);
    cudaFuncSetAttribute(attn_kernel, cudaFuncAttributeMaxDynamicSharedMemorySize, (int)smem);
    attn_kernel<<<dim3(cS / 64, cB * cNH), 256, smem>>>(weights, write_w);

    // Output projection
    sgemm_kernel<<<dim3(cHID / 128, M / 128), 256>>>(pa, wo, out, M, cHID, cHID);
}

// round 3
// speedup vs baseline: 1.2181x; 1.2181x over previous
#include <cuda_runtime.h>
#include <cuda_bf16.h>
#include <math.h>
#include <stdint.h>

// ---------------------------------------------------------------------------
// Problem constants
// ---------------------------------------------------------------------------
namespace {
constexpr int cB   = 2;
constexpr int cS   = 2048;
constexpr int cHID = 2048;
constexpr int cNH  = 16;
constexpr int cNKV = 8;
constexpr int cHD  = 128;
constexpr float cEPS   = 1e-6f;
constexpr float cSCALE = 0.08838834764831845f;  // 128^-0.5
constexpr int cM   = cB * cS;        // 4096
constexpr int cK3  = 3 * cHID;       // 6144  (hi|lo|hi folded K)
}

// ---------------------------------------------------------------------------
// Scratch (device globals -- no runtime allocation allowed)
// ---------------------------------------------------------------------------
__device__ float g_q  [(size_t)cM * cNH  * cHD];   // (b, s, h, d)
__device__ float g_k  [(size_t)cM * cNKV * cHD];
__device__ float g_v  [(size_t)cM * cNKV * cHD];
__device__ float g_att[(size_t)cM * cNH  * cHD];

// bf16 hi/lo-expanded operands
__device__ __nv_bfloat16 g_ahid[(size_t)cM * cK3];      // hidden  [M, 3K] (hi|lo|hi)
__device__ __nv_bfloat16 g_aatt[(size_t)cM * cK3];      // attnout [M, 3K]
__device__ __nv_bfloat16 g_wqt [(size_t)2048 * cK3];    // Wq^T    [N, 3K] (hi|hi|lo)
__device__ __nv_bfloat16 g_wkt [(size_t)1024 * cK3];
__device__ __nv_bfloat16 g_wvt [(size_t)1024 * cK3];
__device__ __nv_bfloat16 g_wot [(size_t)2048 * cK3];

// ---------------------------------------------------------------------------
// PTX helpers (all architecture-portable: sm_80+)
// ---------------------------------------------------------------------------
__device__ __forceinline__ uint32_t smem_u32(const void* p) {
    uint32_t a;
    asm("{ .reg .u64 t; cvta.to.shared.u64 t, %1; cvt.u32.u64 %0, t; }"
        : "=r"(a) : "l"(p));
    return a;
}
__device__ __forceinline__ void cp_async16(uint32_t saddr, const void* gaddr) {
    asm volatile("cp.async.cg.shared.global [%0], [%1], 16;"
                 :: "r"(saddr), "l"(gaddr) : "memory");
}
#define CP_COMMIT()  asm volatile("cp.async.commit_group;" ::: "memory")
#define CP_WAIT(N)   asm volatile("cp.async.wait_group %0;" :: "n"(N) : "memory")

__device__ __forceinline__ void ldm_x4(uint32_t* r, uint32_t addr) {
    asm volatile("ldmatrix.sync.aligned.m8n8.x4.shared.b16 {%0,%1,%2,%3}, [%4];"
                 : "=r"(r[0]), "=r"(r[1]), "=r"(r[2]), "=r"(r[3]) : "r"(addr));
}
__device__ __forceinline__ void ldm_x2(uint32_t* r, uint32_t addr) {
    asm volatile("ldmatrix.sync.aligned.m8n8.x2.shared.b16 {%0,%1}, [%2];"
                 : "=r"(r[0]), "=r"(r[1]) : "r"(addr));
}
__device__ __forceinline__ void mma16816(float* d, const uint32_t* a,
                                         const uint32_t* b) {
    asm volatile(
        "mma.sync.aligned.m16n8k16.row.col.f32.bf16.bf16.f32 "
        "{%0,%1,%2,%3}, {%4,%5,%6,%7}, {%8,%9}, {%0,%1,%2,%3};"
        : "+f"(d[0]), "+f"(d[1]), "+f"(d[2]), "+f"(d[3])
        : "r"(a[0]), "r"(a[1]), "r"(a[2]), "r"(a[3]), "r"(b[0]), "r"(b[1]));
}

// SW128 swizzle on byte offset within a [rows][128B] tile
__device__ __forceinline__ uint32_t sw128(uint32_t off) {
    return off ^ ((off >> 3) & 0x70);
}

// ---------------------------------------------------------------------------
// Conversion kernels (fp32 -> hi/lo bf16 expanded K)
// ---------------------------------------------------------------------------
__global__ __launch_bounds__(256) void cvt_rows_kernel(
    const float* __restrict__ X, __nv_bfloat16* __restrict__ Y, int K)
{
    size_t e = ((size_t)blockIdx.x * 256 + threadIdx.x) * 4;
    float4 x = *(const float4*)(X + e);
    int m = (int)(e / K);
    int k = (int)(e % K);
    float xv[4] = {x.x, x.y, x.z, x.w};
    __nv_bfloat16 hi[4], lo[4];
#pragma unroll
    for (int j = 0; j < 4; j++) {
        hi[j] = __float2bfloat16(xv[j]);
        lo[j] = __float2bfloat16(xv[j] - __bfloat162float(hi[j]));
    }
    size_t base = (size_t)m * (3 * (size_t)K);
    __nv_bfloat162 h01; h01.x = hi[0]; h01.y = hi[1];
    __nv_bfloat162 h23; h23.x = hi[2]; h23.y = hi[3];
    __nv_bfloat162 l01; l01.x = lo[0]; l01.y = lo[1];
    __nv_bfloat162 l23; l23.x = lo[2]; l23.y = lo[3];
    __nv_bfloat162* p0 = (__nv_bfloat162*)(Y + base + k);
    p0[0] = h01; p0[1] = h23;
    __nv_bfloat162* p1 = (__nv_bfloat162*)(Y + base + K + k);
    p1[0] = l01; p1[1] = l23;
    __nv_bfloat162* p2 = (__nv_bfloat162*)(Y + base + 2 * (size_t)K + k);
    p2[0] = h01; p2[1] = h23;
}

__global__ __launch_bounds__(256) void cvt_w_kernel(
    const float* __restrict__ W, __nv_bfloat16* __restrict__ Y, int K, int N)
{
    __shared__ float t[32][33];
    int n0 = blockIdx.x * 32;
    int k0 = blockIdx.y * 32;
    int tx = threadIdx.x;
    int ty = threadIdx.y;
#pragma unroll
    for (int i = 0; i < 32; i += 8)
        t[ty + i][tx] = W[(size_t)(k0 + ty + i) * N + n0 + tx];
    __syncthreads();
#pragma unroll
    for (int i = 0; i < 32; i += 8) {
        int n = n0 + ty + i;
        int k = k0 + tx;
        float x = t[tx][ty + i];
        __nv_bfloat16 hi = __float2bfloat16(x);
        __nv_bfloat16 lo = __float2bfloat16(x - __bfloat162float(hi));
        size_t base = (size_t)n * (3 * (size_t)K);
        Y[base + k]                 = hi;
        Y[base + K + k]             = hi;
        Y[base + 2 * (size_t)K + k] = lo;
    }
}

// ---------------------------------------------------------------------------
// HMMA GEMM: C[M,N] = A[M,K3] @ B[N,K3]^T  (row-major bf16 operands)
// CTA tile 128x128, BK=64, 3-stage cp.async pipeline, SW128 smem,
// 8 warps (2M x 4N), warp tile 64x32, mma.sync m16n8k16 bf16.
// ---------------------------------------------------------------------------
namespace {
constexpr int GBM = 128, GBN = 128, GBK = 64;
constexpr int NSTAGE = 3;
constexpr int TILE_BYTES  = GBM * GBK * 2;        // 16KB
constexpr int STAGE_BYTES = 2 * TILE_BYTES;       // 32KB
constexpr int GEMM_SMEM   = NSTAGE * STAGE_BYTES; // 96KB
}

__device__ __forceinline__ void gemm_load_stage(
    const __nv_bfloat16* __restrict__ Ag, const __nv_bfloat16* __restrict__ Bg,
    int K3, int it, uint32_t stage_base, int tid)
{
    // 128 rows x 128B per tile; 1024 16B-chunks; 256 threads -> 4 chunks each
#pragma unroll
    for (int i = 0; i < 4; i++) {
        int idx = tid + (i << 8);
        int row = idx >> 3;
        int c4  = idx & 7;
        uint32_t sw = sw128((uint32_t)(row * 128 + c4 * 16));
        cp_async16(stage_base + sw,
                   Ag + (size_t)row * K3 + (size_t)it * GBK + c4 * 8);
        cp_async16(stage_base + TILE_BYTES + sw,
                   Bg + (size_t)row * K3 + (size_t)it * GBK + c4 * 8);
    }
}

__global__ __launch_bounds__(256)
void gemm_mma_kernel(const __nv_bfloat16* __restrict__ A,
                     const __nv_bfloat16* __restrict__ B,
                     float* __restrict__ C, int M, int N, int K3)
{
    extern __shared__ char smraw[];
    const uint32_t sbase = smem_u32(smraw);

    const int tid  = threadIdx.x;
    const int wid  = tid >> 5;
    const int lane = tid & 31;
    const int m0 = blockIdx.y * GBM;
    const int n0 = blockIdx.x * GBN;
    const int mw = (wid >> 2) * 64;    // warp M offset in tile
    const int nw = (wid & 3) * 32;     // warp N offset in tile

    const __nv_bfloat16* Ag = A + (size_t)m0 * K3;
    const __nv_bfloat16* Bg = B + (size_t)n0 * K3;
    const int KITERS = K3 / GBK;

    float acc[4][4][4];
#pragma unroll
    for (int i = 0; i < 4; i++)
#pragma unroll
        for (int j = 0; j < 4; j++)
#pragma unroll
            for (int r = 0; r < 4; r++) acc[i][j][r] = 0.f;

    // ldmatrix per-lane address components (within a [128][128B] SW128 tile)
    const int a_row = lane & 15;             // + mw + 16*mi
    const int a_cb  = (lane >> 4) * 16;      // + 32*ks
    const int b_row = lane & 7;              // + nw + 8*nj
    const int b_cb  = ((lane >> 3) & 1) * 16;

    // Prologue: stages 0..NSTAGE-2
#pragma unroll
    for (int s = 0; s < NSTAGE - 1; s++) {
        gemm_load_stage(Ag, Bg, K3, s, sbase + s * STAGE_BYTES, tid);
        CP_COMMIT();
    }

    for (int it = 0; it < KITERS; ++it) {
        CP_WAIT(NSTAGE - 2);
        __syncthreads();

        int nx = it + NSTAGE - 1;
        if (nx < KITERS)
            gemm_load_stage(Ag, Bg, K3, nx,
                            sbase + (nx % NSTAGE) * STAGE_BYTES, tid);
        CP_COMMIT();

        const uint32_t sa = sbase + (it % NSTAGE) * STAGE_BYTES;
        const uint32_t sb = sa + TILE_BYTES;

#pragma unroll
        for (int ks = 0; ks < 4; ks++) {
            uint32_t af[4][4], bf[4][2];
#pragma unroll
            for (int mi = 0; mi < 4; mi++) {
                uint32_t off = (uint32_t)((mw + 16 * mi + a_row) * 128 +
                                          ks * 32 + a_cb);
                ldm_x4(af[mi], sa + sw128(off));
            }
#pragma unroll
            for (int nj = 0; nj < 4; nj++) {
                uint32_t off = (uint32_t)((nw + 8 * nj + b_row) * 128 +
                                          ks * 32 + b_cb);
                ldm_x2(bf[nj], sb + sw128(off));
            }
#pragma unroll
            for (int mi = 0; mi < 4; mi++)
#pragma unroll
                for (int nj = 0; nj < 4; nj++)
                    mma16816(acc[mi][nj], af[mi], bf[nj]);
        }
    }

    // Epilogue: direct STG (fragment layout: thread g=lane/4, t=lane%4)
    const int g = lane >> 2;
    const int t = lane & 3;
#pragma unroll
    for (int mi = 0; mi < 4; mi++) {
#pragma unroll
        for (int nj = 0; nj < 4; nj++) {
            int r0 = m0 + mw + 16 * mi + g;
            int cc = n0 + nw + 8 * nj + t * 2;
            *(float2*)(C + (size_t)r0 * N + cc) =
                make_float2(acc[mi][nj][0], acc[mi][nj][1]);
            *(float2*)(C + (size_t)(r0 + 8) * N + cc) =
                make_float2(acc[mi][nj][2], acc[mi][nj][3]);
        }
    }
}

// ---------------------------------------------------------------------------
// Per-head RMSNorm + RoPE for Q and K (in place on g_q / g_k).
// ---------------------------------------------------------------------------
__global__ __launch_bounds__(128) void norm_rope_kernel(
    const float* __restrict__ cosp, const float* __restrict__ sinp,
    const float* __restrict__ qw,   const float* __restrict__ kw)
{
    const int slot = blockIdx.x % (cNH + cNKV);
    const int bs   = blockIdx.x / (cNH + cNKV);
    const int d    = threadIdx.x;

    float* ptr;
    const float* w;
    if (slot < cNH) { ptr = g_q + ((size_t)bs * cNH  + slot)         * cHD; w = qw; }
    else            { ptr = g_k + ((size_t)bs * cNKV + (slot - cNH)) * cHD; w = kw; }

    float x = ptr[d];
    float v = x * x;
#pragma unroll
    for (int o = 16; o; o >>= 1) v += __shfl_xor_sync(0xffffffffu, v, o);

    __shared__ float wsum[4];
    if ((d & 31) == 0) wsum[d >> 5] = v;
    __syncthreads();
    float var = (wsum[0] + wsum[1] + wsum[2] + wsum[3]) * (1.f / cHD);
    float rs  = rsqrtf(var + cEPS);
    float xn  = x * rs * w[d];

    __shared__ float buf[cHD];
    buf[d] = xn;
    __syncthreads();
    float other = (d < cHD / 2) ? -buf[d + cHD / 2] : buf[d - cHD / 2];

    float cv = cosp[(size_t)bs * cHD + d];
    float sv = sinp[(size_t)bs * cHD + d];
    ptr[d] = xn * cv + other * sv;
}

// ---------------------------------------------------------------------------
// Attention (fp32, two-pass, 64x64 tiles)
// ---------------------------------------------------------------------------
__device__ __forceinline__ void load_tile_T(float* dst, const float* src,
                                            int srcStride, int tid)
{
#pragma unroll
    for (int i = 0; i < 8; i++) {
        int idx = tid + (i << 8);
        int row = idx & 63;
        int c4  = idx >> 6;
        float4 f = *(const float4*)(src + (size_t)row * srcStride + (c4 << 2));
        dst[(c4 * 4 + 0) * 64 + row] = f.x;
        dst[(c4 * 4 + 1) * 64 + row] = f.y;
        dst[(c4 * 4 + 2) * 64 + row] = f.z;
        dst[(c4 * 4 + 3) * 64 + row] = f.w;
    }
}

__device__ __forceinline__ void compute_scores(const float* Qs, const float* Ks,
                                               int r0, int c0, float (&acc)[2][8])
{
#pragma unroll
    for (int i = 0; i < 2; i++)
#pragma unroll
        for (int j = 0; j < 8; j++) acc[i][j] = 0.f;

#pragma unroll 4
    for (int d = 0; d < cHD; d++) {
        float2 qv  = *(const float2*)&Qs[d * 64 + r0];
        float4 k0v = *(const float4*)&Ks[d * 64 + c0];
        float4 k1v = *(const float4*)&Ks[d * 64 + c0 + 4];
        float kv[8] = {k0v.x, k0v.y, k0v.z, k0v.w, k1v.x, k1v.y, k1v.z, k1v.w};
#pragma unroll
        for (int j = 0; j < 8; j++) {
            acc[0][j] += qv.x * kv[j];
            acc[1][j] += qv.y * kv[j];
        }
    }
}

__global__ __launch_bounds__(256) void attn_kernel(float* __restrict__ wout,
                                                   int write_w)
{
    extern __shared__ float sm[];
    float* Qs = sm;
    float* Ks = Qs + 128 * 64;
    float* Vs = Ks + 128 * 64;
    float* Ws = Vs + 64 * 128;

    const int tid = threadIdx.x;
    const int ty  = tid >> 3;
    const int tx  = tid & 7;
    const int bh  = blockIdx.y;
    const int b   = bh >> 4;
    const int h   = bh & 15;
    const int kvh = h >> 1;
    const int q0  = blockIdx.x << 6;
    const int r0  = ty * 2;
    const int c0  = tx * 8;

    const float* qb  = g_q + ((size_t)(b * cS + q0) * cNH + h) * cHD;
    const float* kbb = g_k + ((size_t)(b * cS) * cNKV + kvh) * cHD;
    const float* vbb = g_v + ((size_t)(b * cS) * cNKV + kvh) * cHD;

    load_tile_T(Qs, qb, cNH * cHD, tid);

    const int ktd = q0 >> 6;
    float mr[2] = {-1e30f, -1e30f};
    float lr[2] = {0.f, 0.f};

    for (int kt = 0; kt <= ktd; kt++) {
        __syncthreads();
        load_tile_T(Ks, kbb + (size_t)(kt << 6) * (cNKV * cHD), cNKV * cHD, tid);
        __syncthreads();

        float acc[2][8];
        compute_scores(Qs, Ks, r0, c0, acc);

        const bool diag = (kt == ktd);
#pragma unroll
        for (int i = 0; i < 2; i++) {
#pragma unroll
            for (int j = 0; j < 8; j++) {
                float s = acc[i][j] * cSCALE;
                if (diag && (c0 + j > r0 + i)) s = -1e30f;
                acc[i][j] = s;
            }
            float tm = acc[i][0];
#pragma unroll
            for (int j = 1; j < 8; j++) tm = fmaxf(tm, acc[i][j]);
#pragma unroll
            for (int o = 1; o < 8; o <<= 1)
                tm = fmaxf(tm, __shfl_xor_sync(0xffffffffu, tm, o));
            float mn = fmaxf(mr[i], tm);
            float p = 0.f;
#pragma unroll
            for (int j = 0; j < 8; j++) p += __expf(acc[i][j] - mn);
#pragma unroll
            for (int o = 1; o < 8; o <<= 1)
                p += __shfl_xor_sync(0xffffffffu, p, o);
            lr[i] = lr[i] * __expf(mr[i] - mn) + p;
            mr[i] = mn;
        }
    }

    float invl[2];
#pragma unroll
    for (int i = 0; i < 2; i++) invl[i] = 1.f / lr[i];

    float acco[2][16];
#pragma unroll
    for (int i = 0; i < 2; i++)
#pragma unroll
        for (int j = 0; j < 16; j++) acco[i][j] = 0.f;

    const size_t wbase = ((size_t)(b * cNH + h) * cS + q0) * cS;

    for (int kt = 0; kt <= ktd; kt++) {
        __syncthreads();
        load_tile_T(Ks, kbb + (size_t)(kt << 6) * (cNKV * cHD), cNKV * cHD, tid);
#pragma unroll
        for (int i = 0; i < 8; i++) {
            int idx = tid + (i << 8);
            int row = idx >> 5;
            int c4  = idx & 31;
            const float* vb = vbb + (size_t)((kt << 6) + row) * (cNKV * cHD);
            *(float4*)&Vs[row * 128 + (c4 << 2)] = *(const float4*)(vb + (c4 << 2));
        }
        __syncthreads();

        float acc[2][8];
        compute_scores(Qs, Ks, r0, c0, acc);

        const bool diag = (kt == ktd);
        float w[2][8];
#pragma unroll
        for (int i = 0; i < 2; i++)
#pragma unroll
            for (int j = 0; j < 8; j++) {
                float s  = acc[i][j] * cSCALE;
                float wv = __expf(s - mr[i]) * invl[i];
                if (diag && (c0 + j > r0 + i)) wv = 0.f;
                w[i][j] = wv;
            }

        if (write_w) {
#pragma unroll
            for (int i = 0; i < 2; i++) {
                float* wp = wout + wbase + (size_t)(r0 + i) * cS + (kt << 6) + c0;
                *(float4*)(wp)     = make_float4(w[i][0], w[i][1], w[i][2], w[i][3]);
                *(float4*)(wp + 4) = make_float4(w[i][4], w[i][5], w[i][6], w[i][7]);
            }
        }

#pragma unroll
        for (int i = 0; i < 2; i++)
#pragma unroll
            for (int j = 0; j < 8; j++)
                Ws[(r0 + i) * 65 + c0 + j] = w[i][j];
        __syncthreads();

        const int cc = tx * 16;
#pragma unroll 2
        for (int kk = 0; kk < 64; kk++) {
            float wa = Ws[r0 * 65 + kk];
            float wb = Ws[(r0 + 1) * 65 + kk];
            float4 v0 = *(const float4*)&Vs[kk * 128 + cc];
            float4 v1 = *(const float4*)&Vs[kk * 128 + cc + 4];
            float4 v2 = *(const float4*)&Vs[kk * 128 + cc + 8];
            float4 v3 = *(const float4*)&Vs[kk * 128 + cc + 12];
            float vv[16] = {v0.x, v0.y, v0.z, v0.w, v1.x, v1.y, v1.z, v1.w,
                            v2.x, v2.y, v2.z, v2.w, v3.x, v3.y, v3.z, v3.w};
#pragma unroll
            for (int j = 0; j < 16; j++) {
                acco[0][j] += wa * vv[j];
                acco[1][j] += wb * vv[j];
            }
        }
    }

    if (write_w) {
        int z0 = q0 + 64;
        if (z0 < cS) {
            int zlen4 = (cS - z0) >> 2;
            float4 z4 = make_float4(0.f, 0.f, 0.f, 0.f);
            int tot = 64 * zlen4;
            for (int t = tid; t < tot; t += 256) {
                int r  = t / zlen4;
                int c4 = t - r * zlen4;
                *(float4*)(wout + wbase + (size_t)r * cS + z0 + (c4 << 2)) = z4;
            }
        }
    }

#pragma unroll
    for (int i = 0; i < 2; i++) {
        float* ob = g_att + ((size_t)(b * cS + q0 + r0 + i) * cNH + h) * cHD + tx * 16;
        *(float4*)(ob)      = make_float4(acco[i][0],  acco[i][1],  acco[i][2],  acco[i][3]);
        *(float4*)(ob + 4)  = make_float4(acco[i][4],  acco[i][5],  acco[i][6],  acco[i][7]);
        *(float4*)(ob + 8)  = make_float4(acco[i][8],  acco[i][9],  acco[i][10], acco[i][11]);
        *(float4*)(ob + 12) = make_float4(acco[i][12], acco[i][13], acco[i][14], acco[i][15]);
    }
}

// ---------------------------------------------------------------------------
// Launch
// ---------------------------------------------------------------------------
extern "C" void kernel_launch(void* const* d_in, const int* in_sizes, int n_in,
                              void* d_out, int out_size)
{
    const float* hidden = (const float*)d_in[0];
    const float* cosp   = (const float*)d_in[1];
    const float* sinp   = (const float*)d_in[2];
    const float* wq  = (const float*)d_in[4];
    const float* wk  = (const float*)d_in[5];
    const float* wv  = (const float*)d_in[6];
    const float* wo  = (const float*)d_in[7];
    const float* qnw = (const float*)d_in[8];
    const float* knw = (const float*)d_in[9];

    float* out = (float*)d_out;
    const size_t n_attn = (size_t)cM * cHID;
    const size_t n_w    = (size_t)cB * cNH * cS * cS;
    const int write_w   = ((size_t)out_size >= n_attn + n_w) ? 1 : 0;
    float* weights = out + n_attn;

    float *pq, *pk, *pv, *pa;
    cudaGetSymbolAddress((void**)&pq, g_q);
    cudaGetSymbolAddress((void**)&pk, g_k);
    cudaGetSymbolAddress((void**)&pv, g_v);
    cudaGetSymbolAddress((void**)&pa, g_att);
    __nv_bfloat16 *pahid, *paatt, *pwqt, *pwkt, *pwvt, *pwot;
    cudaGetSymbolAddress((void**)&pahid, g_ahid);
    cudaGetSymbolAddress((void**)&paatt, g_aatt);
    cudaGetSymbolAddress((void**)&pwqt, g_wqt);
    cudaGetSymbolAddress((void**)&pwkt, g_wkt);
    cudaGetSymbolAddress((void**)&pwvt, g_wvt);
    cudaGetSymbolAddress((void**)&pwot, g_wot);

    static bool attr_done = false;
    if (!attr_done) {
        cudaFuncSetAttribute(gemm_mma_kernel,
                             cudaFuncAttributeMaxDynamicSharedMemorySize, GEMM_SMEM);
        const int attn_smem = (128 * 64 + 128 * 64 + 64 * 128 + 64 * 65) * 4;
        cudaFuncSetAttribute(attn_kernel,
                             cudaFuncAttributeMaxDynamicSharedMemorySize, attn_smem);
        attr_done = true;
    }

    // --- operand conversions (hi/lo folded-K bf16) ---
    cvt_rows_kernel<<<(cM * cHID / 4) / 256, 256>>>(hidden, pahid, cHID);
    cvt_w_kernel<<<dim3(2048 / 32, 2048 / 32), dim3(32, 8)>>>(wq, pwqt, 2048, 2048);
    cvt_w_kernel<<<dim3(1024 / 32, 2048 / 32), dim3(32, 8)>>>(wk, pwkt, 2048, 1024);
    cvt_w_kernel<<<dim3(1024 / 32, 2048 / 32), dim3(32, 8)>>>(wv, pwvt, 2048, 1024);
    cvt_w_kernel<<<dim3(2048 / 32, 2048 / 32), dim3(32, 8)>>>(wo, pwot, 2048, 2048);

    // --- QKV projections on HMMA tensor cores ---
    gemm_mma_kernel<<<dim3(2048 / 128, cM / 128), 256, GEMM_SMEM>>>(pahid, pwqt, pq, cM, 2048, cK3);
    gemm_mma_kernel<<<dim3(1024 / 128, cM / 128), 256, GEMM_SMEM>>>(pahid, pwkt, pk, cM, 1024, cK3);
    gemm_mma_kernel<<<dim3(1024 / 128, cM / 128), 256, GEMM_SMEM>>>(pahid, pwvt, pv, cM, 1024, cK3);

    // --- RMSNorm + RoPE ---
    norm_rope_kernel<<<cM * (cNH + cNKV), 128>>>(cosp, sinp, qnw, knw);

    // --- attention ---
    const int attn_smem = (128 * 64 + 128 * 64 + 64 * 128 + 64 * 65) * 4;
    attn_kernel<<<dim3(cS / 64, cB * cNH), 256, attn_smem>>>(weights, write_w);

    // --- output projection ---
    cvt_rows_kernel<<<(cM * cHID / 4) / 256, 256>>>(pa, paatt, cHID);
    gemm_mma_kernel<<<dim3(2048 / 128, cM / 128), 256, GEMM_SMEM>>>(paatt, pwot, out, cM, 2048, cK3);
}

// round 4
// speedup vs baseline: 4.7272x; 3.8809x over previous
#include <cuda_runtime.h>
#include <cuda_bf16.h>
#include <math.h>
#include <stdint.h>

// ---------------------------------------------------------------------------
// Problem constants
// ---------------------------------------------------------------------------
namespace {
constexpr int cB   = 2;
constexpr int cS   = 2048;
constexpr int cHID = 2048;
constexpr int cNH  = 16;
constexpr int cNKV = 8;
constexpr int cHD  = 128;
constexpr float cEPS   = 1e-6f;
constexpr float cSCALE = 0.08838834764831845f;  // 128^-0.5
constexpr int cM   = cB * cS;        // 4096
constexpr int cK3  = 3 * cHID;       // 6144  (hi|lo|hi folded K)
}

// ---------------------------------------------------------------------------
// Scratch (device globals -- no runtime allocation allowed)
// ---------------------------------------------------------------------------
__device__ float g_q  [(size_t)cM * cNH  * cHD];   // (b, s, h, d) fp32 (GEMM out)
__device__ float g_k  [(size_t)cM * cNKV * cHD];
__device__ float g_v  [(size_t)cM * cNKV * cHD];
__device__ float g_att[(size_t)cM * cNH  * cHD];   // attention output pre-Wo
__device__ float g_l  [(size_t)cB * cNH * cS];     // softmax row sums

// bf16 hi/lo planes for attention, head-major layout [b][h][s][d]
__device__ __nv_bfloat16 g_q2hi[(size_t)cB * cNH  * cS * cHD];
__device__ __nv_bfloat16 g_q2lo[(size_t)cB * cNH  * cS * cHD];
__device__ __nv_bfloat16 g_k2hi[(size_t)cB * cNKV * cS * cHD];
__device__ __nv_bfloat16 g_k2lo[(size_t)cB * cNKV * cS * cHD];
__device__ __nv_bfloat16 g_v2hi[(size_t)cB * cNKV * cS * cHD];
__device__ __nv_bfloat16 g_v2lo[(size_t)cB * cNKV * cS * cHD];

// bf16 hi/lo-expanded GEMM operands (folded K)
__device__ __nv_bfloat16 g_ahid[(size_t)cM * cK3];      // hidden  [M, 3K] (hi|lo|hi)
__device__ __nv_bfloat16 g_aatt[(size_t)cM * cK3];      // attnout [M, 3K]
__device__ __nv_bfloat16 g_wqt [(size_t)2048 * cK3];    // Wq^T    [N, 3K] (hi|hi|lo)
__device__ __nv_bfloat16 g_wkt [(size_t)1024 * cK3];
__device__ __nv_bfloat16 g_wvt [(size_t)1024 * cK3];
__device__ __nv_bfloat16 g_wot [(size_t)2048 * cK3];

// ---------------------------------------------------------------------------
// PTX helpers (portable: sm_80+)
// ---------------------------------------------------------------------------
__device__ __forceinline__ uint32_t smem_u32(const void* p) {
    uint32_t a;
    asm("{ .reg .u64 t; cvta.to.shared.u64 t, %1; cvt.u32.u64 %0, t; }"
        : "=r"(a) : "l"(p));
    return a;
}
__device__ __forceinline__ void cp_async16(uint32_t saddr, const void* gaddr) {
    asm volatile("cp.async.cg.shared.global [%0], [%1], 16;"
                 :: "r"(saddr), "l"(gaddr) : "memory");
}
#define CP_COMMIT()  asm volatile("cp.async.commit_group;" ::: "memory")
#define CP_WAIT(N)   asm volatile("cp.async.wait_group %0;" :: "n"(N) : "memory")

__device__ __forceinline__ void ldm_x4(uint32_t* r, uint32_t addr) {
    asm volatile("ldmatrix.sync.aligned.m8n8.x4.shared.b16 {%0,%1,%2,%3}, [%4];"
                 : "=r"(r[0]), "=r"(r[1]), "=r"(r[2]), "=r"(r[3]) : "r"(addr));
}
__device__ __forceinline__ void ldm_x2(uint32_t* r, uint32_t addr) {
    asm volatile("ldmatrix.sync.aligned.m8n8.x2.shared.b16 {%0,%1}, [%2];"
                 : "=r"(r[0]), "=r"(r[1]) : "r"(addr));
}
__device__ __forceinline__ void ldm_x4t(uint32_t* r, uint32_t addr) {
    asm volatile("ldmatrix.sync.aligned.m8n8.x4.trans.shared.b16 {%0,%1,%2,%3}, [%4];"
                 : "=r"(r[0]), "=r"(r[1]), "=r"(r[2]), "=r"(r[3]) : "r"(addr));
}
__device__ __forceinline__ void mma16816(float* d, const uint32_t* a,
                                         const uint32_t* b) {
    asm volatile(
        "mma.sync.aligned.m16n8k16.row.col.f32.bf16.bf16.f32 "
        "{%0,%1,%2,%3}, {%4,%5,%6,%7}, {%8,%9}, {%0,%1,%2,%3};"
        : "+f"(d[0]), "+f"(d[1]), "+f"(d[2]), "+f"(d[3])
        : "r"(a[0]), "r"(a[1]), "r"(a[2]), "r"(a[3]), "r"(b[0]), "r"(b[1]));
}
__device__ __forceinline__ uint32_t sw128(uint32_t off) {
    return off ^ ((off >> 3) & 0x70);
}
__device__ __forceinline__ uint32_t pack_bf16(float lo, float hi) {
    __nv_bfloat162 h2 = __floats2bfloat162_rn(lo, hi);   // lo -> .x (low half)
    return *reinterpret_cast<uint32_t*>(&h2);
}

// ---------------------------------------------------------------------------
// Conversion kernels (fp32 -> hi/lo bf16 expanded K) for the GEMMs
// ---------------------------------------------------------------------------
__global__ __launch_bounds__(256) void cvt_rows_kernel(
    const float* __restrict__ X, __nv_bfloat16* __restrict__ Y, int K)
{
    size_t e = ((size_t)blockIdx.x * 256 + threadIdx.x) * 4;
    float4 x = *(const float4*)(X + e);
    int m = (int)(e / K);
    int k = (int)(e % K);
    float xv[4] = {x.x, x.y, x.z, x.w};
    __nv_bfloat16 hi[4], lo[4];
#pragma unroll
    for (int j = 0; j < 4; j++) {
        hi[j] = __float2bfloat16(xv[j]);
        lo[j] = __float2bfloat16(xv[j] - __bfloat162float(hi[j]));
    }
    size_t base = (size_t)m * (3 * (size_t)K);
    __nv_bfloat162 h01; h01.x = hi[0]; h01.y = hi[1];
    __nv_bfloat162 h23; h23.x = hi[2]; h23.y = hi[3];
    __nv_bfloat162 l01; l01.x = lo[0]; l01.y = lo[1];
    __nv_bfloat162 l23; l23.x = lo[2]; l23.y = lo[3];
    __nv_bfloat162* p0 = (__nv_bfloat162*)(Y + base + k);
    p0[0] = h01; p0[1] = h23;
    __nv_bfloat162* p1 = (__nv_bfloat162*)(Y + base + K + k);
    p1[0] = l01; p1[1] = l23;
    __nv_bfloat162* p2 = (__nv_bfloat162*)(Y + base + 2 * (size_t)K + k);
    p2[0] = h01; p2[1] = h23;
}

__global__ __launch_bounds__(256) void cvt_w_kernel(
    const float* __restrict__ W, __nv_bfloat16* __restrict__ Y, int K, int N)
{
    __shared__ float t[32][33];
    int n0 = blockIdx.x * 32;
    int k0 = blockIdx.y * 32;
    int tx = threadIdx.x;
    int ty = threadIdx.y;
#pragma unroll
    for (int i = 0; i < 32; i += 8)
        t[ty + i][tx] = W[(size_t)(k0 + ty + i) * N + n0 + tx];
    __syncthreads();
#pragma unroll
    for (int i = 0; i < 32; i += 8) {
        int n = n0 + ty + i;
        int k = k0 + tx;
        float x = t[tx][ty + i];
        __nv_bfloat16 hi = __float2bfloat16(x);
        __nv_bfloat16 lo = __float2bfloat16(x - __bfloat162float(hi));
        size_t base = (size_t)n * (3 * (size_t)K);
        Y[base + k]                 = hi;
        Y[base + K + k]             = hi;
        Y[base + 2 * (size_t)K + k] = lo;
    }
}

// ---------------------------------------------------------------------------
// HMMA GEMM (unchanged from R3): C[M,N] = A[M,K3] @ B[N,K3]^T
// ---------------------------------------------------------------------------
namespace {
constexpr int GBM = 128, GBN = 128, GBK = 64;
constexpr int NSTAGE = 3;
constexpr int TILE_BYTES  = GBM * GBK * 2;
constexpr int STAGE_BYTES = 2 * TILE_BYTES;
constexpr int GEMM_SMEM   = NSTAGE * STAGE_BYTES;
}

__device__ __forceinline__ void gemm_load_stage(
    const __nv_bfloat16* __restrict__ Ag, const __nv_bfloat16* __restrict__ Bg,
    int K3, int it, uint32_t stage_base, int tid)
{
#pragma unroll
    for (int i = 0; i < 4; i++) {
        int idx = tid + (i << 8);
        int row = idx >> 3;
        int c4  = idx & 7;
        uint32_t sw = sw128((uint32_t)(row * 128 + c4 * 16));
        cp_async16(stage_base + sw,
                   Ag + (size_t)row * K3 + (size_t)it * GBK + c4 * 8);
        cp_async16(stage_base + TILE_BYTES + sw,
                   Bg + (size_t)row * K3 + (size_t)it * GBK + c4 * 8);
    }
}

__global__ __launch_bounds__(256)
void gemm_mma_kernel(const __nv_bfloat16* __restrict__ A,
                     const __nv_bfloat16* __restrict__ B,
                     float* __restrict__ C, int M, int N, int K3)
{
    extern __shared__ char smraw[];
    const uint32_t sbase = smem_u32(smraw);

    const int tid  = threadIdx.x;
    const int wid  = tid >> 5;
    const int lane = tid & 31;
    const int m0 = blockIdx.y * GBM;
    const int n0 = blockIdx.x * GBN;
    const int mw = (wid >> 2) * 64;
    const int nw = (wid & 3) * 32;

    const __nv_bfloat16* Ag = A + (size_t)m0 * K3;
    const __nv_bfloat16* Bg = B + (size_t)n0 * K3;
    const int KITERS = K3 / GBK;

    float acc[4][4][4];
#pragma unroll
    for (int i = 0; i < 4; i++)
#pragma unroll
        for (int j = 0; j < 4; j++)
#pragma unroll
            for (int r = 0; r < 4; r++) acc[i][j][r] = 0.f;

    const int a_row = lane & 15;
    const int a_cb  = (lane >> 4) * 16;
    const int b_row = lane & 7;
    const int b_cb  = ((lane >> 3) & 1) * 16;

#pragma unroll
    for (int s = 0; s < NSTAGE - 1; s++) {
        gemm_load_stage(Ag, Bg, K3, s, sbase + s * STAGE_BYTES, tid);
        CP_COMMIT();
    }

    for (int it = 0; it < KITERS; ++it) {
        CP_WAIT(NSTAGE - 2);
        __syncthreads();

        int nx = it + NSTAGE - 1;
        if (nx < KITERS)
            gemm_load_stage(Ag, Bg, K3, nx,
                            sbase + (nx % NSTAGE) * STAGE_BYTES, tid);
        CP_COMMIT();

        const uint32_t sa = sbase + (it % NSTAGE) * STAGE_BYTES;
        const uint32_t sb = sa + TILE_BYTES;

#pragma unroll
        for (int ks = 0; ks < 4; ks++) {
            uint32_t af[4][4], bf[4][2];
#pragma unroll
            for (int mi = 0; mi < 4; mi++) {
                uint32_t off = (uint32_t)((mw + 16 * mi + a_row) * 128 +
                                          ks * 32 + a_cb);
                ldm_x4(af[mi], sa + sw128(off));
            }
#pragma unroll
            for (int nj = 0; nj < 4; nj++) {
                uint32_t off = (uint32_t)((nw + 8 * nj + b_row) * 128 +
                                          ks * 32 + b_cb);
                ldm_x2(bf[nj], sb + sw128(off));
            }
#pragma unroll
            for (int mi = 0; mi < 4; mi++)
#pragma unroll
                for (int nj = 0; nj < 4; nj++)
                    mma16816(acc[mi][nj], af[mi], bf[nj]);
        }
    }

    const int g = lane >> 2;
    const int t = lane & 3;
#pragma unroll
    for (int mi = 0; mi < 4; mi++) {
#pragma unroll
        for (int nj = 0; nj < 4; nj++) {
            int r0 = m0 + mw + 16 * mi + g;
            int cc = n0 + nw + 8 * nj + t * 2;
            *(float2*)(C + (size_t)r0 * N + cc) =
                make_float2(acc[mi][nj][0], acc[mi][nj][1]);
            *(float2*)(C + (size_t)(r0 + 8) * N + cc) =
                make_float2(acc[mi][nj][2], acc[mi][nj][3]);
        }
    }
}

// ---------------------------------------------------------------------------
// RMSNorm + RoPE + hi/lo bf16 split. slot 0-15: q heads, 16-23: k, 24-31: v.
// Output layout [b][h][s][d] (head-major for attention).
// ---------------------------------------------------------------------------
__global__ __launch_bounds__(128) void norm_rope_split_kernel(
    const float* __restrict__ cosp, const float* __restrict__ sinp,
    const float* __restrict__ qw,   const float* __restrict__ kw)
{
    const int slot = blockIdx.x & 31;
    const int bs   = blockIdx.x >> 5;
    const int d    = threadIdx.x;
    const int b    = bs >> 11;
    const int s    = bs & 2047;

    float val;
    __nv_bfloat16 *dhi, *dlo;

    if (slot < 24) {
        const float* src;
        const float* w;
        size_t dst;
        if (slot < 16) {
            src = g_q + ((size_t)bs * cNH + slot) * cHD;
            w = qw;
            dst = ((size_t)(b * cNH + slot) * cS + s) * cHD;
            dhi = g_q2hi + dst; dlo = g_q2lo + dst;
        } else {
            src = g_k + ((size_t)bs * cNKV + (slot - 16)) * cHD;
            w = kw;
            dst = ((size_t)(b * cNKV + (slot - 16)) * cS + s) * cHD;
            dhi = g_k2hi + dst; dlo = g_k2lo + dst;
        }
        float x = src[d];
        float v = x * x;
#pragma unroll
        for (int o = 16; o; o >>= 1) v += __shfl_xor_sync(0xffffffffu, v, o);
        __shared__ float wsum[4];
        if ((d & 31) == 0) wsum[d >> 5] = v;
        __syncthreads();
        float var = (wsum[0] + wsum[1] + wsum[2] + wsum[3]) * (1.f / cHD);
        float rs  = rsqrtf(var + cEPS);
        float xn  = x * rs * w[d];

        __shared__ float buf[cHD];
        buf[d] = xn;
        __syncthreads();
        float other = (d < cHD / 2) ? -buf[d + cHD / 2] : buf[d - cHD / 2];
        float cv = cosp[(size_t)bs * cHD + d];
        float sv = sinp[(size_t)bs * cHD + d];
        val = xn * cv + other * sv;
    } else {
        const float* src = g_v + ((size_t)bs * cNKV + (slot - 24)) * cHD;
        size_t dst = ((size_t)(b * cNKV + (slot - 24)) * cS + s) * cHD;
        dhi = g_v2hi + dst; dlo = g_v2lo + dst;
        val = src[d];
    }

    __nv_bfloat16 hi = __float2bfloat16(val);
    __nv_bfloat16 lo = __float2bfloat16(val - __bfloat162float(hi));
    dhi[d] = hi;
    dlo[d] = lo;
}

// ---------------------------------------------------------------------------
// Single-pass MMA attention.
// Grid: (32 q-tiles of 64 rows, B*NKV). Block: 256 threads = 8 warps.
// Warps 0-3: head 2*kvh rows [0,16,32,48]; warps 4-7: head 2*kvh+1.
// No running max needed: |score*scale| <= sqrt(HD)*scale*sqrt(HD) = 11.32.
// Writes UNNORMALIZED p to wout; l to g_l; normalized PV out to g_att.
// ---------------------------------------------------------------------------
namespace {
constexpr int ARS = 136;            // attn smem row stride (bf16): 272B, conflict-free
constexpr int ATB = 64 * ARS * 2;   // 17408 bytes per 64x128 tile
constexpr int ATTN_SMEM = 12 * ATB; // 4 Q tiles + 2 stages x 4 KV tiles = 208896
}

__global__ __launch_bounds__(256, 1)
void attn_mma_kernel(const __nv_bfloat16* __restrict__ qhi_g,
                     const __nv_bfloat16* __restrict__ qlo_g,
                     const __nv_bfloat16* __restrict__ khi_g,
                     const __nv_bfloat16* __restrict__ klo_g,
                     const __nv_bfloat16* __restrict__ vhi_g,
                     const __nv_bfloat16* __restrict__ vlo_g,
                     float* __restrict__ wout,
                     float* __restrict__ lsum,
                     float* __restrict__ outp,
                     int write_w)
{
    extern __shared__ char smraw[];
    const uint32_t uQ  = smem_u32(smraw);
    const uint32_t uKV = uQ + 4 * ATB;

    const int tid  = threadIdx.x;
    const int wid  = tid >> 5;
    const int lane = tid & 31;
    const int qt  = blockIdx.x;
    const int bkv = blockIdx.y;
    const int b   = bkv >> 3;
    const int kvh = bkv & 7;
    const int hs  = wid >> 2;            // head select within kv group
    const int h   = kvh * 2 + hs;
    const int wr  = (wid & 3) * 16;      // warp q-row base within 64-tile
    const int q0  = qt * 64;
    const int g   = lane >> 2;
    const int t   = lane & 3;

    // ---- Q tile loads (4 tiles: h0hi, h0lo, h1hi, h1lo)
    {
        const size_t qrow = ((size_t)(b * cNH + kvh * 2) * cS + q0) * cHD;
        const int row = (tid >> 4);      // row contribution per i below
        const int c   = tid & 15;
#pragma unroll
        for (int i = 0; i < 16; i++) {
            const int tile = i >> 2;
            const int rr = (i & 3) * 16 + row;
            const __nv_bfloat16* base = (tile & 1) ? qlo_g : qhi_g;
            const __nv_bfloat16* src = base + qrow +
                (size_t)(tile >> 1) * cS * cHD + (size_t)rr * cHD + c * 8;
            cp_async16(uQ + tile * ATB + rr * 272 + c * 16, src);
        }
    }
    CP_COMMIT();

    // ---- KV stage 0
    const size_t kvrow0 = ((size_t)(b * cNKV + kvh) * cS) * cHD;
    {
        const int row = (tid >> 4);
        const int c   = tid & 15;
#pragma unroll
        for (int i = 0; i < 16; i++) {
            const int tile = i >> 2;
            const int rr = (i & 3) * 16 + row;
            const __nv_bfloat16* base =
                (tile == 0) ? khi_g : (tile == 1) ? klo_g :
                (tile == 2) ? vhi_g : vlo_g;
            cp_async16(uKV + tile * ATB + rr * 272 + c * 16,
                       base + kvrow0 + (size_t)rr * cHD + c * 8);
        }
    }
    CP_COMMIT();

    // ldmatrix per-lane offsets
    const uint32_t qoff = (uint32_t)((wr + (lane & 15)) * 272 + (lane >> 4) * 16);
    const uint32_t koff = (uint32_t)(((lane & 7) + ((lane >> 4) & 1) * 8) * 272 +
                                     ((lane >> 3) & 1) * 16);
    const uint32_t voff = (uint32_t)(((lane & 7) + ((lane >> 3) & 1) * 8) * 272 +
                                     (lane >> 4) * 16);
    const uint32_t uQh = uQ + hs * 2 * ATB;
    const uint32_t uQl = uQh + ATB;

    float oacc[16][4];
#pragma unroll
    for (int i = 0; i < 16; i++)
#pragma unroll
        for (int r = 0; r < 4; r++) oacc[i][r] = 0.f;
    float l0 = 0.f, l1 = 0.f;

    for (int kt = 0; kt <= qt; kt++) {
        // prefetch next KV stage
        if (kt < qt) {
            const int st = (kt + 1) & 1;
            const size_t kvrow = kvrow0 + (size_t)((kt + 1) * 64) * cHD;
            const int row = (tid >> 4);
            const int c   = tid & 15;
#pragma unroll
            for (int i = 0; i < 16; i++) {
                const int tile = i >> 2;
                const int rr = (i & 3) * 16 + row;
                const __nv_bfloat16* base =
                    (tile == 0) ? khi_g : (tile == 1) ? klo_g :
                    (tile == 2) ? vhi_g : vlo_g;
                cp_async16(uKV + st * 4 * ATB + tile * ATB + rr * 272 + c * 16,
                           base + kvrow + (size_t)rr * cHD + c * 8);
            }
            CP_COMMIT();
            CP_WAIT(1);
        } else {
            CP_WAIT(0);
        }
        __syncthreads();

        const uint32_t ukv  = uKV + (kt & 1) * 4 * ATB;
        const uint32_t ukhi = ukv;
        const uint32_t uklo = ukv + ATB;
        const uint32_t uvhi = ukv + 2 * ATB;
        const uint32_t uvlo = ukv + 3 * ATB;

        // ---------- QK: 3-term hi/lo ----------
        float sacc[8][4];
#pragma unroll
        for (int i = 0; i < 8; i++)
#pragma unroll
            for (int r = 0; r < 4; r++) sacc[i][r] = 0.f;

#pragma unroll
        for (int kk = 0; kk < 8; kk++) {
            uint32_t qh[4], ql[4];
            ldm_x4(qh, uQh + qoff + kk * 32);
            ldm_x4(ql, uQl + qoff + kk * 32);
#pragma unroll
            for (int njp = 0; njp < 4; njp++) {
                uint32_t kb[4];
                ldm_x4(kb, ukhi + njp * (16 * 272) + koff + kk * 32);
                mma16816(sacc[2 * njp],     qh, kb);
                mma16816(sacc[2 * njp + 1], qh, kb + 2);
                mma16816(sacc[2 * njp],     ql, kb);
                mma16816(sacc[2 * njp + 1], ql, kb + 2);
            }
#pragma unroll
            for (int njp = 0; njp < 4; njp++) {
                uint32_t kb[4];
                ldm_x4(kb, uklo + njp * (16 * 272) + koff + kk * 32);
                mma16816(sacc[2 * njp],     qh, kb);
                mma16816(sacc[2 * njp + 1], qh, kb + 2);
            }
        }

        // ---------- exp, mask, row sums, weight write, bf16 split ----------
        const bool diag = (kt == qt);
        uint32_t ahi[4][4], alo[4][4];
#pragma unroll
        for (int nj = 0; nj < 8; nj++) {
            float p0 = __expf(sacc[nj][0] * cSCALE);
            float p1 = __expf(sacc[nj][1] * cSCALE);
            float p2 = __expf(sacc[nj][2] * cSCALE);
            float p3 = __expf(sacc[nj][3] * cSCALE);
            if (diag) {
                const int cbase = nj * 8 + 2 * t;
                const int rlo = wr + g, rhi = wr + 8 + g;
                if (cbase     > rlo) p0 = 0.f;
                if (cbase + 1 > rlo) p1 = 0.f;
                if (cbase     > rhi) p2 = 0.f;
                if (cbase + 1 > rhi) p3 = 0.f;
            }
            l0 += p0 + p1;
            l1 += p2 + p3;
            if (write_w) {
                float* wp = wout + ((size_t)(b * cNH + h) * cS + q0 + wr + g) * cS
                            + kt * 64 + nj * 8 + 2 * t;
                *(float2*)wp = make_float2(p0, p1);
                *(float2*)(wp + 8 * (size_t)cS) = make_float2(p2, p3);
            }
            // split p into bf16 hi/lo A-fragments
            float h0 = __bfloat162float(__float2bfloat16(p0));
            float h1 = __bfloat162float(__float2bfloat16(p1));
            float h2 = __bfloat162float(__float2bfloat16(p2));
            float h3 = __bfloat162float(__float2bfloat16(p3));
            const int kkB = nj >> 1;
            const int sub = (nj & 1) * 2;
            ahi[kkB][sub]     = pack_bf16(h0, h1);
            ahi[kkB][sub + 1] = pack_bf16(h2, h3);
            alo[kkB][sub]     = pack_bf16(p0 - h0, p1 - h1);
            alo[kkB][sub + 1] = pack_bf16(p2 - h2, p3 - h3);
        }

        // ---------- PV: 3-term hi/lo ----------
#pragma unroll
        for (int kk = 0; kk < 4; kk++) {
#pragma unroll
            for (int ndp = 0; ndp < 8; ndp++) {
                uint32_t vb[4];
                ldm_x4t(vb, uvhi + kk * (16 * 272) + ndp * 32 + voff);
                mma16816(oacc[2 * ndp],     ahi[kk], vb);
                mma16816(oacc[2 * ndp + 1], ahi[kk], vb + 2);
                mma16816(oacc[2 * ndp],     alo[kk], vb);
                mma16816(oacc[2 * ndp + 1], alo[kk], vb + 2);
            }
#pragma unroll
            for (int ndp = 0; ndp < 8; ndp++) {
                uint32_t vb[4];
                ldm_x4t(vb, uvlo + kk * (16 * 272) + ndp * 32 + voff);
                mma16816(oacc[2 * ndp],     ahi[kk], vb);
                mma16816(oacc[2 * ndp + 1], ahi[kk], vb + 2);
            }
        }
        __syncthreads();
    }

    // ---- finalize: full row sums, 1/l, write out + l
    l0 += __shfl_xor_sync(0xffffffffu, l0, 1);
    l0 += __shfl_xor_sync(0xffffffffu, l0, 2);
    l1 += __shfl_xor_sync(0xffffffffu, l1, 1);
    l1 += __shfl_xor_sync(0xffffffffu, l1, 2);
    const float inv0 = 1.f / l0;
    const float inv1 = 1.f / l1;

    if (write_w && t == 0) {
        lsum[(size_t)(b * cNH + h) * cS + q0 + wr + g]     = l0;
        lsum[(size_t)(b * cNH + h) * cS + q0 + wr + 8 + g] = l1;
    }

#pragma unroll
    for (int nd = 0; nd < 16; nd++) {
        const int col = nd * 8 + 2 * t;
        float* o0 = outp + ((size_t)(b * cS + q0 + wr + g) * cNH + h) * cHD + col;
        float* o1 = outp + ((size_t)(b * cS + q0 + wr + 8 + g) * cNH + h) * cHD + col;
        *(float2*)o0 = make_float2(oacc[nd][0] * inv0, oacc[nd][1] * inv0);
        *(float2*)o1 = make_float2(oacc[nd][2] * inv1, oacc[nd][3] * inv1);
    }
}

// ---------------------------------------------------------------------------
// Normalize weights rows by 1/l; zero the never-written upper triangle.
// One block per (b,h,q) row.
// ---------------------------------------------------------------------------
__global__ __launch_bounds__(256) void norm_weights_kernel(
    float* __restrict__ w, const float* __restrict__ lsum)
{
    const int row = blockIdx.x;            // (b*NH + h)*S + q
    const int q   = row & (cS - 1);
    const int valid = ((q >> 6) + 1) << 6; // multiple of 64
    const float inv = 1.f / lsum[row];
    float* wr = w + (size_t)row * cS;
    const int tid = threadIdx.x;
#pragma unroll
    for (int i = 0; i < 2; i++) {
        int c = (tid + i * 256) * 4;
        if (c < valid) {
            float4 v = *(float4*)(wr + c);
            v.x *= inv; v.y *= inv; v.z *= inv; v.w *= inv;
            *(float4*)(wr + c) = v;
        } else {
            *(float4*)(wr + c) = make_float4(0.f, 0.f, 0.f, 0.f);
        }
    }
}

// ---------------------------------------------------------------------------
// Launch
// ---------------------------------------------------------------------------
extern "C" void kernel_launch(void* const* d_in, const int* in_sizes, int n_in,
                              void* d_out, int out_size)
{
    const float* hidden = (const float*)d_in[0];
    const float* cosp   = (const float*)d_in[1];
    const float* sinp   = (const float*)d_in[2];
    const float* wq  = (const float*)d_in[4];
    const float* wk  = (const float*)d_in[5];
    const float* wv  = (const float*)d_in[6];
    const float* wo  = (const float*)d_in[7];
    const float* qnw = (const float*)d_in[8];
    const float* knw = (const float*)d_in[9];

    float* out = (float*)d_out;
    const size_t n_attn = (size_t)cM * cHID;
    const size_t n_w    = (size_t)cB * cNH * cS * cS;
    const int write_w   = ((size_t)out_size >= n_attn + n_w) ? 1 : 0;
    float* weights = out + n_attn;

    float *pq, *pk, *pv, *pa, *pl;
    cudaGetSymbolAddress((void**)&pq, g_q);
    cudaGetSymbolAddress((void**)&pk, g_k);
    cudaGetSymbolAddress((void**)&pv, g_v);
    cudaGetSymbolAddress((void**)&pa, g_att);
    cudaGetSymbolAddress((void**)&pl, g_l);
    __nv_bfloat16 *pahid, *paatt, *pwqt, *pwkt, *pwvt, *pwot;
    cudaGetSymbolAddress((void**)&pahid, g_ahid);
    cudaGetSymbolAddress((void**)&paatt, g_aatt);
    cudaGetSymbolAddress((void**)&pwqt, g_wqt);
    cudaGetSymbolAddress((void**)&pwkt, g_wkt);
    cudaGetSymbolAddress((void**)&pwvt, g_wvt);
    cudaGetSymbolAddress((void**)&pwot, g_wot);
    __nv_bfloat16 *pqh, *pql, *pkh, *pklo, *pvh, *pvlo;
    cudaGetSymbolAddress((void**)&pqh,  g_q2hi);
    cudaGetSymbolAddress((void**)&pql,  g_q2lo);
    cudaGetSymbolAddress((void**)&pkh,  g_k2hi);
    cudaGetSymbolAddress((void**)&pklo, g_k2lo);
    cudaGetSymbolAddress((void**)&pvh,  g_v2hi);
    cudaGetSymbolAddress((void**)&pvlo, g_v2lo);

    static bool attr_done = false;
    if (!attr_done) {
        cudaFuncSetAttribute(gemm_mma_kernel,
                             cudaFuncAttributeMaxDynamicSharedMemorySize, GEMM_SMEM);
        cudaFuncSetAttribute(attn_mma_kernel,
                             cudaFuncAttributeMaxDynamicSharedMemorySize, ATTN_SMEM);
        attr_done = true;
    }

    // --- GEMM operand conversions (hi/lo folded-K bf16) ---
    cvt_rows_kernel<<<(cM * cHID / 4) / 256, 256>>>(hidden, pahid, cHID);
    cvt_w_kernel<<<dim3(2048 / 32, 2048 / 32), dim3(32, 8)>>>(wq, pwqt, 2048, 2048);
    cvt_w_kernel<<<dim3(1024 / 32, 2048 / 32), dim3(32, 8)>>>(wk, pwkt, 2048, 1024);
    cvt_w_kernel<<<dim3(1024 / 32, 2048 / 32), dim3(32, 8)>>>(wv, pwvt, 2048, 1024);
    cvt_w_kernel<<<dim3(2048 / 32, 2048 / 32), dim3(32, 8)>>>(wo, pwot, 2048, 2048);

    // --- QKV projections on HMMA tensor cores ---
    gemm_mma_kernel<<<dim3(2048 / 128, cM / 128), 256, GEMM_SMEM>>>(pahid, pwqt, pq, cM, 2048, cK3);
    gemm_mma_kernel<<<dim3(1024 / 128, cM / 128), 256, GEMM_SMEM>>>(pahid, pwkt, pk, cM, 1024, cK3);
    gemm_mma_kernel<<<dim3(1024 / 128, cM / 128), 256, GEMM_SMEM>>>(pahid, pwvt, pv, cM, 1024, cK3);

    // --- RMSNorm + RoPE + bf16 hi/lo split into head-major layout ---
    norm_rope_split_kernel<<<cM * 32, 128>>>(cosp, sinp, qnw, knw);

    // --- single-pass MMA attention ---
    attn_mma_kernel<<<dim3(cS / 64, cB * cNKV), 256, ATTN_SMEM>>>(
        pqh, pql, pkh, pklo, pvh, pvlo, weights, pl, pa, write_w);

    // --- normalize weights + zero upper triangle ---
    if (write_w)
        norm_weights_kernel<<<cB * cNH * cS, 256>>>(weights, pl);

    // --- output projection ---
    cvt_rows_kernel<<<(cM * cHID / 4) / 256, 256>>>(pa, paatt, cHID);
    gemm_mma_kernel<<<dim3(2048 / 128, cM / 128), 256, GEMM_SMEM>>>(paatt, pwot, out, cM, 2048, cK3);
}

// round 5
// speedup vs baseline: 6.2596x; 1.3241x over previous
#include <cuda_runtime.h>
#include <cuda_bf16.h>
#include <math.h>
#include <stdint.h>

// ---------------------------------------------------------------------------
// Problem constants
// ---------------------------------------------------------------------------
namespace {
constexpr int cB   = 2;
constexpr int cS   = 2048;
constexpr int cHID = 2048;
constexpr int cNH  = 16;
constexpr int cNKV = 8;
constexpr int cHD  = 128;
constexpr float cEPS   = 1e-6f;
constexpr float cSCALE = 0.08838834764831845f;  // 128^-0.5
constexpr int cM   = cB * cS;        // 4096
constexpr int cNQKV = 4096;          // fused QKV output width (2048+1024+1024)
}

// ---------------------------------------------------------------------------
// Scratch (device globals -- no runtime allocation allowed)
// ---------------------------------------------------------------------------
__device__ float g_ahf [(size_t)cM * cHID];        // tf32-rounded hidden
__device__ float g_qkv [(size_t)cM * cNQKV];       // fused QKV projection out
__device__ float g_att [(size_t)cM * cNH * cHD];   // attn out pre-Wo (tf32-rounded)
__device__ float g_wt  [(size_t)cNQKV * cHID];     // [wq|wk|wv]^T tf32-rounded
__device__ float g_wot [(size_t)cHID * cHID];      // wo^T tf32-rounded
__device__ float g_l   [(size_t)cB * cNH * cS];    // softmax row sums

// bf16 hi/lo planes for attention, head-major layout [b][h][s][d]
__device__ __nv_bfloat16 g_q2hi[(size_t)cB * cNH  * cS * cHD];
__device__ __nv_bfloat16 g_q2lo[(size_t)cB * cNH  * cS * cHD];
__device__ __nv_bfloat16 g_k2hi[(size_t)cB * cNKV * cS * cHD];
__device__ __nv_bfloat16 g_k2lo[(size_t)cB * cNKV * cS * cHD];
__device__ __nv_bfloat16 g_v2hi[(size_t)cB * cNKV * cS * cHD];
__device__ __nv_bfloat16 g_v2lo[(size_t)cB * cNKV * cS * cHD];

// ---------------------------------------------------------------------------
// PTX helpers (portable: sm_80+)
// ---------------------------------------------------------------------------
__device__ __forceinline__ uint32_t smem_u32(const void* p) {
    uint32_t a;
    asm("{ .reg .u64 t; cvta.to.shared.u64 t, %1; cvt.u32.u64 %0, t; }"
        : "=r"(a) : "l"(p));
    return a;
}
__device__ __forceinline__ void cp_async16(uint32_t saddr, const void* gaddr) {
    asm volatile("cp.async.cg.shared.global [%0], [%1], 16;"
                 :: "r"(saddr), "l"(gaddr) : "memory");
}
#define CP_COMMIT()  asm volatile("cp.async.commit_group;" ::: "memory")
#define CP_WAIT(N)   asm volatile("cp.async.wait_group %0;" :: "n"(N) : "memory")

__device__ __forceinline__ void ldm_x4(uint32_t* r, uint32_t addr) {
    asm volatile("ldmatrix.sync.aligned.m8n8.x4.shared.b16 {%0,%1,%2,%3}, [%4];"
                 : "=r"(r[0]), "=r"(r[1]), "=r"(r[2]), "=r"(r[3]) : "r"(addr));
}
__device__ __forceinline__ void ldm_x2(uint32_t* r, uint32_t addr) {
    asm volatile("ldmatrix.sync.aligned.m8n8.x2.shared.b16 {%0,%1}, [%2];"
                 : "=r"(r[0]), "=r"(r[1]) : "r"(addr));
}
__device__ __forceinline__ void ldm_x4t(uint32_t* r, uint32_t addr) {
    asm volatile("ldmatrix.sync.aligned.m8n8.x4.trans.shared.b16 {%0,%1,%2,%3}, [%4];"
                 : "=r"(r[0]), "=r"(r[1]), "=r"(r[2]), "=r"(r[3]) : "r"(addr));
}
__device__ __forceinline__ void mma16816(float* d, const uint32_t* a,
                                         const uint32_t* b) {
    asm volatile(
        "mma.sync.aligned.m16n8k16.row.col.f32.bf16.bf16.f32 "
        "{%0,%1,%2,%3}, {%4,%5,%6,%7}, {%8,%9}, {%0,%1,%2,%3};"
        : "+f"(d[0]), "+f"(d[1]), "+f"(d[2]), "+f"(d[3])
        : "r"(a[0]), "r"(a[1]), "r"(a[2]), "r"(a[3]), "r"(b[0]), "r"(b[1]));
}
__device__ __forceinline__ void mma1688_tf32(float* d, const uint32_t* a,
                                             const uint32_t* b) {
    asm volatile(
        "mma.sync.aligned.m16n8k8.row.col.f32.tf32.tf32.f32 "
        "{%0,%1,%2,%3}, {%4,%5,%6,%7}, {%8,%9}, {%0,%1,%2,%3};"
        : "+f"(d[0]), "+f"(d[1]), "+f"(d[2]), "+f"(d[3])
        : "r"(a[0]), "r"(a[1]), "r"(a[2]), "r"(a[3]), "r"(b[0]), "r"(b[1]));
}
__device__ __forceinline__ uint32_t sw128(uint32_t off) {
    return off ^ ((off >> 3) & 0x70);
}
__device__ __forceinline__ uint32_t pack_bf16(float lo, float hi) {
    __nv_bfloat162 h2 = __floats2bfloat162_rn(lo, hi);
    return *reinterpret_cast<uint32_t*>(&h2);
}
__device__ __forceinline__ float tf32r(float x) {
    uint32_t u;
    asm("cvt.rna.tf32.f32 %0, %1;" : "=r"(u) : "f"(x));
    return __uint_as_float(u);
}

// ---------------------------------------------------------------------------
// Prep kernels
// ---------------------------------------------------------------------------
// Elementwise tf32 rounding copy (A operand of QKV GEMM).
__global__ __launch_bounds__(256) void round_tf32_kernel(
    const float* __restrict__ X, float* __restrict__ Y)
{
    size_t e = ((size_t)blockIdx.x * 256 + threadIdx.x) * 4;
    float4 x = *(const float4*)(X + e);
    x.x = tf32r(x.x); x.y = tf32r(x.y); x.z = tf32r(x.z); x.w = tf32r(x.w);
    *(float4*)(Y + e) = x;
}

// Weight transpose + tf32 round: W [K,N] row-major -> Y [N,K] row-major.
__global__ __launch_bounds__(256) void cvt_wT_kernel(
    const float* __restrict__ W, float* __restrict__ Y, int K, int N)
{
    __shared__ float t[32][33];
    int n0 = blockIdx.x * 32;
    int k0 = blockIdx.y * 32;
    int tx = threadIdx.x;
    int ty = threadIdx.y;
#pragma unroll
    for (int i = 0; i < 32; i += 8)
        t[ty + i][tx] = W[(size_t)(k0 + ty + i) * N + n0 + tx];
    __syncthreads();
#pragma unroll
    for (int i = 0; i < 32; i += 8) {
        int n = n0 + ty + i;
        int k = k0 + tx;
        Y[(size_t)n * K + k] = tf32r(t[tx][ty + i]);
    }
}

// ---------------------------------------------------------------------------
// TF32 HMMA GEMM: C[M,N] = A[M,K] @ B[N,K]^T (row-major fp32, tf32-prerounded)
// CTA tile 128x128, BK=32 (128B rows), 3-stage cp.async, SW128,
// 8 warps (2M x 4N), warp tile 64x32, mma.sync m16n8k8 tf32.
// ---------------------------------------------------------------------------
namespace {
constexpr int GBM = 128, GBN = 128, GBK = 32;     // GBK in fp32 elements
constexpr int NSTAGE = 3;
constexpr int TILE_BYTES  = GBM * GBK * 4;        // 16KB
constexpr int STAGE_BYTES = 2 * TILE_BYTES;       // 32KB
constexpr int GEMM_SMEM   = NSTAGE * STAGE_BYTES; // 96KB
}

__device__ __forceinline__ void gemm_load_stage(
    const float* __restrict__ Ag, const float* __restrict__ Bg,
    int K, int it, uint32_t stage_base, int tid)
{
#pragma unroll
    for (int i = 0; i < 4; i++) {
        int idx = tid + (i << 8);
        int row = idx >> 3;
        int c4  = idx & 7;
        uint32_t sw = sw128((uint32_t)(row * 128 + c4 * 16));
        cp_async16(stage_base + sw,
                   Ag + (size_t)row * K + (size_t)it * GBK + c4 * 4);
        cp_async16(stage_base + TILE_BYTES + sw,
                   Bg + (size_t)row * K + (size_t)it * GBK + c4 * 4);
    }
}

__global__ __launch_bounds__(256)
void gemm_tf32_kernel(const float* __restrict__ A,
                      const float* __restrict__ B,
                      float* __restrict__ C, int M, int N, int K)
{
    extern __shared__ char smraw[];
    const uint32_t sbase = smem_u32(smraw);

    const int tid  = threadIdx.x;
    const int wid  = tid >> 5;
    const int lane = tid & 31;
    const int m0 = blockIdx.y * GBM;
    const int n0 = blockIdx.x * GBN;
    const int mw = (wid >> 2) * 64;
    const int nw = (wid & 3) * 32;

    const float* Ag = A + (size_t)m0 * K;
    const float* Bg = B + (size_t)n0 * K;
    const int KITERS = K / GBK;

    float acc[4][4][4];
#pragma unroll
    for (int i = 0; i < 4; i++)
#pragma unroll
        for (int j = 0; j < 4; j++)
#pragma unroll
            for (int r = 0; r < 4; r++) acc[i][j][r] = 0.f;

    const int a_row = lane & 15;
    const int a_cb  = (lane >> 4) * 16;
    const int b_row = lane & 7;
    const int b_cb  = ((lane >> 3) & 1) * 16;

#pragma unroll
    for (int s = 0; s < NSTAGE - 1; s++) {
        gemm_load_stage(Ag, Bg, K, s, sbase + s * STAGE_BYTES, tid);
        CP_COMMIT();
    }

    for (int it = 0; it < KITERS; ++it) {
        CP_WAIT(NSTAGE - 2);
        __syncthreads();

        int nx = it + NSTAGE - 1;
        if (nx < KITERS)
            gemm_load_stage(Ag, Bg, K, nx,
                            sbase + (nx % NSTAGE) * STAGE_BYTES, tid);
        CP_COMMIT();

        const uint32_t sa = sbase + (it % NSTAGE) * STAGE_BYTES;
        const uint32_t sb = sa + TILE_BYTES;

#pragma unroll
        for (int ks = 0; ks < 4; ks++) {              // 4 x k8 per BK=32
            uint32_t af[4][4], bf[4][2];
#pragma unroll
            for (int mi = 0; mi < 4; mi++) {
                uint32_t off = (uint32_t)((mw + 16 * mi + a_row) * 128 +
                                          ks * 32 + a_cb);
                ldm_x4(af[mi], sa + sw128(off));
            }
#pragma unroll
            for (int nj = 0; nj < 4; nj++) {
                uint32_t off = (uint32_t)((nw + 8 * nj + b_row) * 128 +
                                          ks * 32 + b_cb);
                ldm_x2(bf[nj], sb + sw128(off));
            }
#pragma unroll
            for (int mi = 0; mi < 4; mi++)
#pragma unroll
                for (int nj = 0; nj < 4; nj++)
                    mma1688_tf32(acc[mi][nj], af[mi], bf[nj]);
        }
    }

    const int g = lane >> 2;
    const int t = lane & 3;
#pragma unroll
    for (int mi = 0; mi < 4; mi++) {
#pragma unroll
        for (int nj = 0; nj < 4; nj++) {
            int r0 = m0 + mw + 16 * mi + g;
            int cc = n0 + nw + 8 * nj + t * 2;
            *(float2*)(C + (size_t)r0 * N + cc) =
                make_float2(acc[mi][nj][0], acc[mi][nj][1]);
            *(float2*)(C + (size_t)(r0 + 8) * N + cc) =
                make_float2(acc[mi][nj][2], acc[mi][nj][3]);
        }
    }
}

// ---------------------------------------------------------------------------
// RMSNorm + RoPE + hi/lo bf16 split, reading fused QKV buffer.
// slot 0-15: q heads, 16-23: k, 24-31: v. Output [b][h][s][d] head-major.
// ---------------------------------------------------------------------------
__global__ __launch_bounds__(128) void norm_rope_split_kernel(
    const float* __restrict__ cosp, const float* __restrict__ sinp,
    const float* __restrict__ qw,   const float* __restrict__ kw)
{
    const int slot = blockIdx.x & 31;
    const int bs   = blockIdx.x >> 5;
    const int d    = threadIdx.x;
    const int b    = bs >> 11;
    const int s    = bs & 2047;

    float val;
    __nv_bfloat16 *dhi, *dlo;

    if (slot < 24) {
        const float* src;
        const float* w;
        size_t dst;
        if (slot < 16) {
            src = g_qkv + (size_t)bs * cNQKV + slot * cHD;
            w = qw;
            dst = ((size_t)(b * cNH + slot) * cS + s) * cHD;
            dhi = g_q2hi + dst; dlo = g_q2lo + dst;
        } else {
            src = g_qkv + (size_t)bs * cNQKV + 2048 + (slot - 16) * cHD;
            w = kw;
            dst = ((size_t)(b * cNKV + (slot - 16)) * cS + s) * cHD;
            dhi = g_k2hi + dst; dlo = g_k2lo + dst;
        }
        float x = src[d];
        float v = x * x;
#pragma unroll
        for (int o = 16; o; o >>= 1) v += __shfl_xor_sync(0xffffffffu, v, o);
        __shared__ float wsum[4];
        if ((d & 31) == 0) wsum[d >> 5] = v;
        __syncthreads();
        float var = (wsum[0] + wsum[1] + wsum[2] + wsum[3]) * (1.f / cHD);
        float rs  = rsqrtf(var + cEPS);
        float xn  = x * rs * w[d];

        __shared__ float buf[cHD];
        buf[d] = xn;
        __syncthreads();
        float other = (d < cHD / 2) ? -buf[d + cHD / 2] : buf[d - cHD / 2];
        float cv = cosp[(size_t)bs * cHD + d];
        float sv = sinp[(size_t)bs * cHD + d];
        val = xn * cv + other * sv;
    } else {
        const float* src = g_qkv + (size_t)bs * cNQKV + 3072 + (slot - 24) * cHD;
        size_t dst = ((size_t)(b * cNKV + (slot - 24)) * cS + s) * cHD;
        dhi = g_v2hi + dst; dlo = g_v2lo + dst;
        val = src[d];
    }

    __nv_bfloat16 hi = __float2bfloat16(val);
    __nv_bfloat16 lo = __float2bfloat16(val - __bfloat162float(hi));
    dhi[d] = hi;
    dlo[d] = lo;
}

// ---------------------------------------------------------------------------
// Single-pass MMA attention (bf16 3-term hi/lo; unchanged from R4 except
// the output is tf32-rounded so it can feed the Wo tf32 GEMM directly).
// ---------------------------------------------------------------------------
namespace {
constexpr int ARS = 136;
constexpr int ATB = 64 * ARS * 2;
constexpr int ATTN_SMEM = 12 * ATB;
}

__global__ __launch_bounds__(256, 1)
void attn_mma_kernel(const __nv_bfloat16* __restrict__ qhi_g,
                     const __nv_bfloat16* __restrict__ qlo_g,
                     const __nv_bfloat16* __restrict__ khi_g,
                     const __nv_bfloat16* __restrict__ klo_g,
                     const __nv_bfloat16* __restrict__ vhi_g,
                     const __nv_bfloat16* __restrict__ vlo_g,
                     float* __restrict__ wout,
                     float* __restrict__ lsum,
                     float* __restrict__ outp,
                     int write_w)
{
    extern __shared__ char smraw[];
    const uint32_t uQ  = smem_u32(smraw);
    const uint32_t uKV = uQ + 4 * ATB;

    const int tid  = threadIdx.x;
    const int wid  = tid >> 5;
    const int lane = tid & 31;
    const int qt  = blockIdx.x;
    const int bkv = blockIdx.y;
    const int b   = bkv >> 3;
    const int kvh = bkv & 7;
    const int hs  = wid >> 2;
    const int h   = kvh * 2 + hs;
    const int wr  = (wid & 3) * 16;
    const int q0  = qt * 64;
    const int g   = lane >> 2;
    const int t   = lane & 3;

    {
        const size_t qrow = ((size_t)(b * cNH + kvh * 2) * cS + q0) * cHD;
        const int row = (tid >> 4);
        const int c   = tid & 15;
#pragma unroll
        for (int i = 0; i < 16; i++) {
            const int tile = i >> 2;
            const int rr = (i & 3) * 16 + row;
            const __nv_bfloat16* base = (tile & 1) ? qlo_g : qhi_g;
            const __nv_bfloat16* src = base + qrow +
                (size_t)(tile >> 1) * cS * cHD + (size_t)rr * cHD + c * 8;
            cp_async16(uQ + tile * ATB + rr * 272 + c * 16, src);
        }
    }
    CP_COMMIT();

    const size_t kvrow0 = ((size_t)(b * cNKV + kvh) * cS) * cHD;
    {
        const int row = (tid >> 4);
        const int c   = tid & 15;
#pragma unroll
        for (int i = 0; i < 16; i++) {
            const int tile = i >> 2;
            const int rr = (i & 3) * 16 + row;
            const __nv_bfloat16* base =
                (tile == 0) ? khi_g : (tile == 1) ? klo_g :
                (tile == 2) ? vhi_g : vlo_g;
            cp_async16(uKV + tile * ATB + rr * 272 + c * 16,
                       base + kvrow0 + (size_t)rr * cHD + c * 8);
        }
    }
    CP_COMMIT();

    const uint32_t qoff = (uint32_t)((wr + (lane & 15)) * 272 + (lane >> 4) * 16);
    const uint32_t koff = (uint32_t)(((lane & 7) + ((lane >> 4) & 1) * 8) * 272 +
                                     ((lane >> 3) & 1) * 16);
    const uint32_t voff = (uint32_t)(((lane & 7) + ((lane >> 3) & 1) * 8) * 272 +
                                     (lane >> 4) * 16);
    const uint32_t uQh = uQ + hs * 2 * ATB;
    const uint32_t uQl = uQh + ATB;

    float oacc[16][4];
#pragma unroll
    for (int i = 0; i < 16; i++)
#pragma unroll
        for (int r = 0; r < 4; r++) oacc[i][r] = 0.f;
    float l0 = 0.f, l1 = 0.f;

    for (int kt = 0; kt <= qt; kt++) {
        if (kt < qt) {
            const int st = (kt + 1) & 1;
            const size_t kvrow = kvrow0 + (size_t)((kt + 1) * 64) * cHD;
            const int row = (tid >> 4);
            const int c   = tid & 15;
#pragma unroll
            for (int i = 0; i < 16; i++) {
                const int tile = i >> 2;
                const int rr = (i & 3) * 16 + row;
                const __nv_bfloat16* base =
                    (tile == 0) ? khi_g : (tile == 1) ? klo_g :
                    (tile == 2) ? vhi_g : vlo_g;
                cp_async16(uKV + st * 4 * ATB + tile * ATB + rr * 272 + c * 16,
                           base + kvrow + (size_t)rr * cHD + c * 8);
            }
            CP_COMMIT();
            CP_WAIT(1);
        } else {
            CP_WAIT(0);
        }
        __syncthreads();

        const uint32_t ukv  = uKV + (kt & 1) * 4 * ATB;
        const uint32_t ukhi = ukv;
        const uint32_t uklo = ukv + ATB;
        const uint32_t uvhi = ukv + 2 * ATB;
        const uint32_t uvlo = ukv + 3 * ATB;

        float sacc[8][4];
#pragma unroll
        for (int i = 0; i < 8; i++)
#pragma unroll
            for (int r = 0; r < 4; r++) sacc[i][r] = 0.f;

#pragma unroll
        for (int kk = 0; kk < 8; kk++) {
            uint32_t qh[4], ql[4];
            ldm_x4(qh, uQh + qoff + kk * 32);
            ldm_x4(ql, uQl + qoff + kk * 32);
#pragma unroll
            for (int njp = 0; njp < 4; njp++) {
                uint32_t kb[4];
                ldm_x4(kb, ukhi + njp * (16 * 272) + koff + kk * 32);
                mma16816(sacc[2 * njp],     qh, kb);
                mma16816(sacc[2 * njp + 1], qh, kb + 2);
                mma16816(sacc[2 * njp],     ql, kb);
                mma16816(sacc[2 * njp + 1], ql, kb + 2);
            }
#pragma unroll
            for (int njp = 0; njp < 4; njp++) {
                uint32_t kb[4];
                ldm_x4(kb, uklo + njp * (16 * 272) + koff + kk * 32);
                mma16816(sacc[2 * njp],     qh, kb);
                mma16816(sacc[2 * njp + 1], qh, kb + 2);
            }
        }

        const bool diag = (kt == qt);
        uint32_t ahi[4][4], alo[4][4];
#pragma unroll
        for (int nj = 0; nj < 8; nj++) {
            float p0 = __expf(sacc[nj][0] * cSCALE);
            float p1 = __expf(sacc[nj][1] * cSCALE);
            float p2 = __expf(sacc[nj][2] * cSCALE);
            float p3 = __expf(sacc[nj][3] * cSCALE);
            if (diag) {
                const int cbase = nj * 8 + 2 * t;
                const int rlo = wr + g, rhi = wr + 8 + g;
                if (cbase     > rlo) p0 = 0.f;
                if (cbase + 1 > rlo) p1 = 0.f;
                if (cbase     > rhi) p2 = 0.f;
                if (cbase + 1 > rhi) p3 = 0.f;
            }
            l0 += p0 + p1;
            l1 += p2 + p3;
            if (write_w) {
                float* wp = wout + ((size_t)(b * cNH + h) * cS + q0 + wr + g) * cS
                            + kt * 64 + nj * 8 + 2 * t;
                *(float2*)wp = make_float2(p0, p1);
                *(float2*)(wp + 8 * (size_t)cS) = make_float2(p2, p3);
            }
            float h0 = __bfloat162float(__float2bfloat16(p0));
            float h1 = __bfloat162float(__float2bfloat16(p1));
            float h2 = __bfloat162float(__float2bfloat16(p2));
            float h3 = __bfloat162float(__float2bfloat16(p3));
            const int kkB = nj >> 1;
            const int sub = (nj & 1) * 2;
            ahi[kkB][sub]     = pack_bf16(h0, h1);
            ahi[kkB][sub + 1] = pack_bf16(h2, h3);
            alo[kkB][sub]     = pack_bf16(p0 - h0, p1 - h1);
            alo[kkB][sub + 1] = pack_bf16(p2 - h2, p3 - h3);
        }

#pragma unroll
        for (int kk = 0; kk < 4; kk++) {
#pragma unroll
            for (int ndp = 0; ndp < 8; ndp++) {
                uint32_t vb[4];
                ldm_x4t(vb, uvhi + kk * (16 * 272) + ndp * 32 + voff);
                mma16816(oacc[2 * ndp],     ahi[kk], vb);
                mma16816(oacc[2 * ndp + 1], ahi[kk], vb + 2);
                mma16816(oacc[2 * ndp],     alo[kk], vb);
                mma16816(oacc[2 * ndp + 1], alo[kk], vb + 2);
            }
#pragma unroll
            for (int ndp = 0; ndp < 8; ndp++) {
                uint32_t vb[4];
                ldm_x4t(vb, uvlo + kk * (16 * 272) + ndp * 32 + voff);
                mma16816(oacc[2 * ndp],     ahi[kk], vb);
                mma16816(oacc[2 * ndp + 1], ahi[kk], vb + 2);
            }
        }
        __syncthreads();
    }

    l0 += __shfl_xor_sync(0xffffffffu, l0, 1);
    l0 += __shfl_xor_sync(0xffffffffu, l0, 2);
    l1 += __shfl_xor_sync(0xffffffffu, l1, 1);
    l1 += __shfl_xor_sync(0xffffffffu, l1, 2);
    const float inv0 = 1.f / l0;
    const float inv1 = 1.f / l1;

    if (write_w && t == 0) {
        lsum[(size_t)(b * cNH + h) * cS + q0 + wr + g]     = l0;
        lsum[(size_t)(b * cNH + h) * cS + q0 + wr + 8 + g] = l1;
    }

#pragma unroll
    for (int nd = 0; nd < 16; nd++) {
        const int col = nd * 8 + 2 * t;
        float* o0 = outp + ((size_t)(b * cS + q0 + wr + g) * cNH + h) * cHD + col;
        float* o1 = outp + ((size_t)(b * cS + q0 + wr + 8 + g) * cNH + h) * cHD + col;
        *(float2*)o0 = make_float2(tf32r(oacc[nd][0] * inv0),
                                   tf32r(oacc[nd][1] * inv0));
        *(float2*)o1 = make_float2(tf32r(oacc[nd][2] * inv1),
                                   tf32r(oacc[nd][3] * inv1));
    }
}

// ---------------------------------------------------------------------------
// Normalize weights rows by 1/l; zero the never-written upper triangle.
// ---------------------------------------------------------------------------
__global__ __launch_bounds__(256) void norm_weights_kernel(
    float* __restrict__ w, const float* __restrict__ lsum)
{
    const int row = blockIdx.x;
    const int q   = row & (cS - 1);
    const int valid = ((q >> 6) + 1) << 6;
    const float inv = 1.f / lsum[row];
    float* wr = w + (size_t)row * cS;
    const int tid = threadIdx.x;
#pragma unroll
    for (int i = 0; i < 2; i++) {
        int c = (tid + i * 256) * 4;
        if (c < valid) {
            float4 v = *(float4*)(wr + c);
            v.x *= inv; v.y *= inv; v.z *= inv; v.w *= inv;
            *(float4*)(wr + c) = v;
        } else {
            *(float4*)(wr + c) = make_float4(0.f, 0.f, 0.f, 0.f);
        }
    }
}

// ---------------------------------------------------------------------------
// Launch
// ---------------------------------------------------------------------------
extern "C" void kernel_launch(void* const* d_in, const int* in_sizes, int n_in,
                              void* d_out, int out_size)
{
    const float* hidden = (const float*)d_in[0];
    const float* cosp   = (const float*)d_in[1];
    const float* sinp   = (const float*)d_in[2];
    const float* wq  = (const float*)d_in[4];
    const float* wk  = (const float*)d_in[5];
    const float* wv  = (const float*)d_in[6];
    const float* wo  = (const float*)d_in[7];
    const float* qnw = (const float*)d_in[8];
    const float* knw = (const float*)d_in[9];

    float* out = (float*)d_out;
    const size_t n_attn = (size_t)cM * cHID;
    const size_t n_w    = (size_t)cB * cNH * cS * cS;
    const int write_w   = ((size_t)out_size >= n_attn + n_w) ? 1 : 0;
    float* weights = out + n_attn;

    float *pahf, *pqkv, *pa, *pwt, *pwot, *pl;
    cudaGetSymbolAddress((void**)&pahf, g_ahf);
    cudaGetSymbolAddress((void**)&pqkv, g_qkv);
    cudaGetSymbolAddress((void**)&pa,   g_att);
    cudaGetSymbolAddress((void**)&pwt,  g_wt);
    cudaGetSymbolAddress((void**)&pwot, g_wot);
    cudaGetSymbolAddress((void**)&pl,   g_l);
    __nv_bfloat16 *pqh, *pql, *pkh, *pklo, *pvh, *pvlo;
    cudaGetSymbolAddress((void**)&pqh,  g_q2hi);
    cudaGetSymbolAddress((void**)&pql,  g_q2lo);
    cudaGetSymbolAddress((void**)&pkh,  g_k2hi);
    cudaGetSymbolAddress((void**)&pklo, g_k2lo);
    cudaGetSymbolAddress((void**)&pvh,  g_v2hi);
    cudaGetSymbolAddress((void**)&pvlo, g_v2lo);

    static bool attr_done = false;
    if (!attr_done) {
        cudaFuncSetAttribute(gemm_tf32_kernel,
                             cudaFuncAttributeMaxDynamicSharedMemorySize, GEMM_SMEM);
        cudaFuncSetAttribute(attn_mma_kernel,
                             cudaFuncAttributeMaxDynamicSharedMemorySize, ATTN_SMEM);
        attr_done = true;
    }

    // --- prep: tf32-rounded A, transposed+rounded weights ---
    round_tf32_kernel<<<(cM * cHID / 4) / 256, 256>>>(hidden, pahf);
    cvt_wT_kernel<<<dim3(2048 / 32, 2048 / 32), dim3(32, 8)>>>(
        wq, pwt, cHID, 2048);
    cvt_wT_kernel<<<dim3(1024 / 32, 2048 / 32), dim3(32, 8)>>>(
        wk, pwt + (size_t)2048 * cHID, cHID, 1024);
    cvt_wT_kernel<<<dim3(1024 / 32, 2048 / 32), dim3(32, 8)>>>(
        wv, pwt + (size_t)3072 * cHID, cHID, 1024);
    cvt_wT_kernel<<<dim3(2048 / 32, 2048 / 32), dim3(32, 8)>>>(
        wo, pwot, cHID, 2048);

    // --- fused QKV projection (tf32) ---
    gemm_tf32_kernel<<<dim3(cNQKV / 128, cM / 128), 256, GEMM_SMEM>>>(
        pahf, pwt, pqkv, cM, cNQKV, cHID);

    // --- RMSNorm + RoPE + bf16 hi/lo split into head-major layout ---
    norm_rope_split_kernel<<<cM * 32, 128>>>(cosp, sinp, qnw, knw);

    // --- single-pass MMA attention ---
    attn_mma_kernel<<<dim3(cS / 64, cB * cNKV), 256, ATTN_SMEM>>>(
        pqh, pql, pkh, pklo, pvh, pvlo, weights, pl, pa, write_w);

    // --- normalize weights + zero upper triangle ---
    if (write_w)
        norm_weights_kernel<<<cB * cNH * cS, 256>>>(weights, pl);

    // --- output projection (tf32) ---
    gemm_tf32_kernel<<<dim3(cHID / 128, cM / 128), 256, GEMM_SMEM>>>(
        pa, pwot, out, cM, cHID, cHID);
}

// round 6
// speedup vs baseline: 6.4785x; 1.0350x over previous
#include <cuda_runtime.h>
#include <cuda_bf16.h>
#include <math.h>
#include <stdint.h>

// ---------------------------------------------------------------------------
// Problem constants
// ---------------------------------------------------------------------------
namespace {
constexpr int cB   = 2;
constexpr int cS   = 2048;
constexpr int cHID = 2048;
constexpr int cNH  = 16;
constexpr int cNKV = 8;
constexpr int cHD  = 128;
constexpr float cEPS   = 1e-6f;
constexpr float cSCALE = 0.08838834764831845f;  // 128^-0.5
constexpr int cM   = cB * cS;        // 4096
constexpr int cNQKV = 4096;          // fused QKV output width (2048+1024+1024)
}

// ---------------------------------------------------------------------------
// Scratch (device globals -- no runtime allocation allowed)
// ---------------------------------------------------------------------------
__device__ float g_ahf [(size_t)cM * cHID];        // tf32-rounded hidden
__device__ float g_qkv [(size_t)cM * cNQKV];       // fused QKV projection out
__device__ float g_att [(size_t)cM * cNH * cHD];   // attn out pre-Wo (tf32-rounded)
__device__ float g_wt  [(size_t)cNQKV * cHID];     // [wq|wk|wv]^T tf32-rounded
__device__ float g_wot [(size_t)cHID * cHID];      // wo^T tf32-rounded
__device__ float g_l   [(size_t)cB * cNH * cS];    // softmax row sums

// bf16 hi/lo planes for attention, head-major layout [b][h][s][d]
__device__ __nv_bfloat16 g_q2hi[(size_t)cB * cNH  * cS * cHD];
__device__ __nv_bfloat16 g_q2lo[(size_t)cB * cNH  * cS * cHD];
__device__ __nv_bfloat16 g_k2hi[(size_t)cB * cNKV * cS * cHD];
__device__ __nv_bfloat16 g_k2lo[(size_t)cB * cNKV * cS * cHD];
__device__ __nv_bfloat16 g_v2hi[(size_t)cB * cNKV * cS * cHD];
__device__ __nv_bfloat16 g_v2lo[(size_t)cB * cNKV * cS * cHD];

// ---------------------------------------------------------------------------
// PTX helpers (portable: sm_80+)
// ---------------------------------------------------------------------------
__device__ __forceinline__ uint32_t smem_u32(const void* p) {
    uint32_t a;
    asm("{ .reg .u64 t; cvta.to.shared.u64 t, %1; cvt.u32.u64 %0, t; }"
        : "=r"(a) : "l"(p));
    return a;
}
__device__ __forceinline__ void cp_async16(uint32_t saddr, const void* gaddr) {
    asm volatile("cp.async.cg.shared.global [%0], [%1], 16;"
                 :: "r"(saddr), "l"(gaddr) : "memory");
}
#define CP_COMMIT()  asm volatile("cp.async.commit_group;" ::: "memory")
#define CP_WAIT(N)   asm volatile("cp.async.wait_group %0;" :: "n"(N) : "memory")

__device__ __forceinline__ void ldm_x4(uint32_t* r, uint32_t addr) {
    asm volatile("ldmatrix.sync.aligned.m8n8.x4.shared.b16 {%0,%1,%2,%3}, [%4];"
                 : "=r"(r[0]), "=r"(r[1]), "=r"(r[2]), "=r"(r[3]) : "r"(addr));
}
__device__ __forceinline__ void ldm_x4t(uint32_t* r, uint32_t addr) {
    asm volatile("ldmatrix.sync.aligned.m8n8.x4.trans.shared.b16 {%0,%1,%2,%3}, [%4];"
                 : "=r"(r[0]), "=r"(r[1]), "=r"(r[2]), "=r"(r[3]) : "r"(addr));
}
__device__ __forceinline__ void mma16816(float* d, const uint32_t* a,
                                         const uint32_t* b) {
    asm volatile(
        "mma.sync.aligned.m16n8k16.row.col.f32.bf16.bf16.f32 "
        "{%0,%1,%2,%3}, {%4,%5,%6,%7}, {%8,%9}, {%0,%1,%2,%3};"
        : "+f"(d[0]), "+f"(d[1]), "+f"(d[2]), "+f"(d[3])
        : "r"(a[0]), "r"(a[1]), "r"(a[2]), "r"(a[3]), "r"(b[0]), "r"(b[1]));
}
__device__ __forceinline__ void mma1688_tf32(float* d, const uint32_t* a,
                                             const uint32_t* b) {
    asm volatile(
        "mma.sync.aligned.m16n8k8.row.col.f32.tf32.tf32.f32 "
        "{%0,%1,%2,%3}, {%4,%5,%6,%7}, {%8,%9}, {%0,%1,%2,%3};"
        : "+f"(d[0]), "+f"(d[1]), "+f"(d[2]), "+f"(d[3])
        : "r"(a[0]), "r"(a[1]), "r"(a[2]), "r"(a[3]), "r"(b[0]), "r"(b[1]));
}
__device__ __forceinline__ uint32_t sw128(uint32_t off) {
    return off ^ ((off >> 3) & 0x70);
}
__device__ __forceinline__ uint32_t pack_bf16(float lo, float hi) {
    __nv_bfloat162 h2 = __floats2bfloat162_rn(lo, hi);
    return *reinterpret_cast<uint32_t*>(&h2);
}
__device__ __forceinline__ float tf32r(float x) {
    uint32_t u;
    asm("cvt.rna.tf32.f32 %0, %1;" : "=r"(u) : "f"(x));
    return __uint_as_float(u);
}

// ---------------------------------------------------------------------------
// Prep kernels
// ---------------------------------------------------------------------------
__global__ __launch_bounds__(256) void round_tf32_kernel(
    const float* __restrict__ X, float* __restrict__ Y)
{
    size_t e = ((size_t)blockIdx.x * 256 + threadIdx.x) * 4;
    float4 x = *(const float4*)(X + e);
    x.x = tf32r(x.x); x.y = tf32r(x.y); x.z = tf32r(x.z); x.w = tf32r(x.w);
    *(float4*)(Y + e) = x;
}

__global__ __launch_bounds__(256) void cvt_wT_kernel(
    const float* __restrict__ W, float* __restrict__ Y, int K, int N)
{
    __shared__ float t[32][33];
    int n0 = blockIdx.x * 32;
    int k0 = blockIdx.y * 32;
    int tx = threadIdx.x;
    int ty = threadIdx.y;
#pragma unroll
    for (int i = 0; i < 32; i += 8)
        t[ty + i][tx] = W[(size_t)(k0 + ty + i) * N + n0 + tx];
    __syncthreads();
#pragma unroll
    for (int i = 0; i < 32; i += 8) {
        int n = n0 + ty + i;
        int k = k0 + tx;
        Y[(size_t)n * K + k] = tf32r(t[tx][ty + i]);
    }
}

// ---------------------------------------------------------------------------
// TF32 HMMA GEMM: C[M,N] = A[M,K] @ B[N,K]^T (row-major fp32, tf32-prerounded)
// CTA tile 128x256, BK=32, 3-stage cp.async, SW128.
// 8 warps in a 2(M) x 4(N) grid, warp tile 64x64, mma.sync m16n8k8 tf32.
// ---------------------------------------------------------------------------
namespace {
constexpr int GBM = 128, GBN = 256, GBK = 32;       // GBK in fp32 elements
constexpr int NSTAGE = 3;
constexpr int A_BYTES = GBM * GBK * 4;              // 16KB
constexpr int B_BYTES = GBN * GBK * 4;              // 32KB
constexpr int STAGE_BYTES = A_BYTES + B_BYTES;      // 48KB
constexpr int GEMM_SMEM   = NSTAGE * STAGE_BYTES;   // 144KB
}

__device__ __forceinline__ void gemm_load_stage(
    const float* __restrict__ Ag, const float* __restrict__ Bg,
    int K, int it, uint32_t stage_base, int tid)
{
    // A: 128 rows x 128B = 1024 16B-chunks
#pragma unroll
    for (int i = 0; i < 4; i++) {
        int idx = tid + (i << 8);
        int row = idx >> 3;
        int c4  = idx & 7;
        uint32_t sw = sw128((uint32_t)(row * 128 + c4 * 16));
        cp_async16(stage_base + sw,
                   Ag + (size_t)row * K + (size_t)it * GBK + c4 * 4);
    }
    // B: 256 rows x 128B = 2048 16B-chunks
#pragma unroll
    for (int i = 0; i < 8; i++) {
        int idx = tid + (i << 8);
        int row = idx >> 3;
        int c4  = idx & 7;
        uint32_t sw = sw128((uint32_t)(row * 128 + c4 * 16));
        cp_async16(stage_base + A_BYTES + sw,
                   Bg + (size_t)row * K + (size_t)it * GBK + c4 * 4);
    }
}

__global__ __launch_bounds__(256, 1)
void gemm_tf32_kernel(const float* __restrict__ A,
                      const float* __restrict__ B,
                      float* __restrict__ C, int M, int N, int K)
{
    extern __shared__ char smraw[];
    const uint32_t sbase = smem_u32(smraw);

    const int tid  = threadIdx.x;
    const int wid  = tid >> 5;
    const int lane = tid & 31;
    const int m0 = blockIdx.y * GBM;
    const int n0 = blockIdx.x * GBN;
    const int mw = (wid >> 2) * 64;       // warp M offset (0,64)
    const int nw = (wid & 3) * 64;        // warp N offset (0..192)

    const float* Ag = A + (size_t)m0 * K;
    const float* Bg = B + (size_t)n0 * K;
    const int KITERS = K / GBK;

    float acc[4][8][4];
#pragma unroll
    for (int i = 0; i < 4; i++)
#pragma unroll
        for (int j = 0; j < 8; j++)
#pragma unroll
            for (int r = 0; r < 4; r++) acc[i][j][r] = 0.f;

    // ldmatrix per-lane address components
    const int a_row = lane & 15;
    const int a_cb  = (lane >> 4) * 16;
    const int b_row = (lane & 7) + ((lane >> 4) & 1) * 8;   // paired-x4 B
    const int b_cb  = ((lane >> 3) & 1) * 16;

#pragma unroll
    for (int s = 0; s < NSTAGE - 1; s++) {
        gemm_load_stage(Ag, Bg, K, s, sbase + s * STAGE_BYTES, tid);
        CP_COMMIT();
    }

    for (int it = 0; it < KITERS; ++it) {
        CP_WAIT(NSTAGE - 2);
        __syncthreads();

        int nx = it + NSTAGE - 1;
        if (nx < KITERS)
            gemm_load_stage(Ag, Bg, K, nx,
                            sbase + (nx % NSTAGE) * STAGE_BYTES, tid);
        CP_COMMIT();

        const uint32_t sa = sbase + (it % NSTAGE) * STAGE_BYTES;
        const uint32_t sb = sa + A_BYTES;

#pragma unroll
        for (int ks = 0; ks < 4; ks++) {              // 4 x k8 per BK=32
            uint32_t af[4][4], bf[4][4];
#pragma unroll
            for (int mi = 0; mi < 4; mi++) {
                uint32_t off = (uint32_t)((mw + 16 * mi + a_row) * 128 +
                                          ks * 32 + a_cb);
                ldm_x4(af[mi], sa + sw128(off));
            }
#pragma unroll
            for (int njp = 0; njp < 4; njp++) {       // each x4 covers 2 n-tiles
                uint32_t off = (uint32_t)((nw + 16 * njp + b_row) * 128 +
                                          ks * 32 + b_cb);
                ldm_x4(bf[njp], sb + sw128(off));
            }
#pragma unroll
            for (int mi = 0; mi < 4; mi++)
#pragma unroll
                for (int njp = 0; njp < 4; njp++) {
                    mma1688_tf32(acc[mi][2 * njp],     af[mi], bf[njp]);
                    mma1688_tf32(acc[mi][2 * njp + 1], af[mi], bf[njp] + 2);
                }
        }
    }

    const int g = lane >> 2;
    const int t = lane & 3;
#pragma unroll
    for (int mi = 0; mi < 4; mi++) {
#pragma unroll
        for (int nj = 0; nj < 8; nj++) {
            int r0 = m0 + mw + 16 * mi + g;
            int cc = n0 + nw + 8 * nj + t * 2;
            *(float2*)(C + (size_t)r0 * N + cc) =
                make_float2(acc[mi][nj][0], acc[mi][nj][1]);
            *(float2*)(C + (size_t)(r0 + 8) * N + cc) =
                make_float2(acc[mi][nj][2], acc[mi][nj][3]);
        }
    }
}

// ---------------------------------------------------------------------------
// RMSNorm + RoPE + hi/lo bf16 split, reading fused QKV buffer.
// ---------------------------------------------------------------------------
__global__ __launch_bounds__(128) void norm_rope_split_kernel(
    const float* __restrict__ cosp, const float* __restrict__ sinp,
    const float* __restrict__ qw,   const float* __restrict__ kw)
{
    const int slot = blockIdx.x & 31;
    const int bs   = blockIdx.x >> 5;
    const int d    = threadIdx.x;
    const int b    = bs >> 11;
    const int s    = bs & 2047;

    float val;
    __nv_bfloat16 *dhi, *dlo;

    if (slot < 24) {
        const float* src;
        const float* w;
        size_t dst;
        if (slot < 16) {
            src = g_qkv + (size_t)bs * cNQKV + slot * cHD;
            w = qw;
            dst = ((size_t)(b * cNH + slot) * cS + s) * cHD;
            dhi = g_q2hi + dst; dlo = g_q2lo + dst;
        } else {
            src = g_qkv + (size_t)bs * cNQKV + 2048 + (slot - 16) * cHD;
            w = kw;
            dst = ((size_t)(b * cNKV + (slot - 16)) * cS + s) * cHD;
            dhi = g_k2hi + dst; dlo = g_k2lo + dst;
        }
        float x = src[d];
        float v = x * x;
#pragma unroll
        for (int o = 16; o; o >>= 1) v += __shfl_xor_sync(0xffffffffu, v, o);
        __shared__ float wsum[4];
        if ((d & 31) == 0) wsum[d >> 5] = v;
        __syncthreads();
        float var = (wsum[0] + wsum[1] + wsum[2] + wsum[3]) * (1.f / cHD);
        float rs  = rsqrtf(var + cEPS);
        float xn  = x * rs * w[d];

        __shared__ float buf[cHD];
        buf[d] = xn;
        __syncthreads();
        float other = (d < cHD / 2) ? -buf[d + cHD / 2] : buf[d - cHD / 2];
        float cv = cosp[(size_t)bs * cHD + d];
        float sv = sinp[(size_t)bs * cHD + d];
        val = xn * cv + other * sv;
    } else {
        const float* src = g_qkv + (size_t)bs * cNQKV + 3072 + (slot - 24) * cHD;
        size_t dst = ((size_t)(b * cNKV + (slot - 24)) * cS + s) * cHD;
        dhi = g_v2hi + dst; dlo = g_v2lo + dst;
        val = src[d];
    }

    __nv_bfloat16 hi = __float2bfloat16(val);
    __nv_bfloat16 lo = __float2bfloat16(val - __bfloat162float(hi));
    dhi[d] = hi;
    dlo[d] = lo;
}

// ---------------------------------------------------------------------------
// Single-pass MMA attention (bf16 3-term hi/lo).
// ---------------------------------------------------------------------------
namespace {
constexpr int ARS = 136;
constexpr int ATB = 64 * ARS * 2;
constexpr int ATTN_SMEM = 12 * ATB;
}

__global__ __launch_bounds__(256, 1)
void attn_mma_kernel(const __nv_bfloat16* __restrict__ qhi_g,
                     const __nv_bfloat16* __restrict__ qlo_g,
                     const __nv_bfloat16* __restrict__ khi_g,
                     const __nv_bfloat16* __restrict__ klo_g,
                     const __nv_bfloat16* __restrict__ vhi_g,
                     const __nv_bfloat16* __restrict__ vlo_g,
                     float* __restrict__ wout,
                     float* __restrict__ lsum,
                     float* __restrict__ outp,
                     int write_w)
{
    extern __shared__ char smraw[];
    const uint32_t uQ  = smem_u32(smraw);
    const uint32_t uKV = uQ + 4 * ATB;

    const int tid  = threadIdx.x;
    const int wid  = tid >> 5;
    const int lane = tid & 31;
    const int qt  = blockIdx.x;
    const int bkv = blockIdx.y;
    const int b   = bkv >> 3;
    const int kvh = bkv & 7;
    const int hs  = wid >> 2;
    const int h   = kvh * 2 + hs;
    const int wr  = (wid & 3) * 16;
    const int q0  = qt * 64;
    const int g   = lane >> 2;
    const int t   = lane & 3;

    {
        const size_t qrow = ((size_t)(b * cNH + kvh * 2) * cS + q0) * cHD;
        const int row = (tid >> 4);
        const int c   = tid & 15;
#pragma unroll
        for (int i = 0; i < 16; i++) {
            const int tile = i >> 2;
            const int rr = (i & 3) * 16 + row;
            const __nv_bfloat16* base = (tile & 1) ? qlo_g : qhi_g;
            const __nv_bfloat16* src = base + qrow +
                (size_t)(tile >> 1) * cS * cHD + (size_t)rr * cHD + c * 8;
            cp_async16(uQ + tile * ATB + rr * 272 + c * 16, src);
        }
    }
    CP_COMMIT();

    const size_t kvrow0 = ((size_t)(b * cNKV + kvh) * cS) * cHD;
    {
        const int row = (tid >> 4);
        const int c   = tid & 15;
#pragma unroll
        for (int i = 0; i < 16; i++) {
            const int tile = i >> 2;
            const int rr = (i & 3) * 16 + row;
            const __nv_bfloat16* base =
                (tile == 0) ? khi_g : (tile == 1) ? klo_g :
                (tile == 2) ? vhi_g : vlo_g;
            cp_async16(uKV + tile * ATB + rr * 272 + c * 16,
                       base + kvrow0 + (size_t)rr * cHD + c * 8);
        }
    }
    CP_COMMIT();

    const uint32_t qoff = (uint32_t)((wr + (lane & 15)) * 272 + (lane >> 4) * 16);
    const uint32_t koff = (uint32_t)(((lane & 7) + ((lane >> 4) & 1) * 8) * 272 +
                                     ((lane >> 3) & 1) * 16);
    const uint32_t voff = (uint32_t)(((lane & 7) + ((lane >> 3) & 1) * 8) * 272 +
                                     (lane >> 4) * 16);
    const uint32_t uQh = uQ + hs * 2 * ATB;
    const uint32_t uQl = uQh + ATB;

    float oacc[16][4];
#pragma unroll
    for (int i = 0; i < 16; i++)
#pragma unroll
        for (int r = 0; r < 4; r++) oacc[i][r] = 0.f;
    float l0 = 0.f, l1 = 0.f;

    for (int kt = 0; kt <= qt; kt++) {
        if (kt < qt) {
            const int st = (kt + 1) & 1;
            const size_t kvrow = kvrow0 + (size_t)((kt + 1) * 64) * cHD;
            const int row = (tid >> 4);
            const int c   = tid & 15;
#pragma unroll
            for (int i = 0; i < 16; i++) {
                const int tile = i >> 2;
                const int rr = (i & 3) * 16 + row;
                const __nv_bfloat16* base =
                    (tile == 0) ? khi_g : (tile == 1) ? klo_g :
                    (tile == 2) ? vhi_g : vlo_g;
                cp_async16(uKV + st * 4 * ATB + tile * ATB + rr * 272 + c * 16,
                           base + kvrow + (size_t)rr * cHD + c * 8);
            }
            CP_COMMIT();
            CP_WAIT(1);
        } else {
            CP_WAIT(0);
        }
        __syncthreads();

        const uint32_t ukv  = uKV + (kt & 1) * 4 * ATB;
        const uint32_t ukhi = ukv;
        const uint32_t uklo = ukv + ATB;
        const uint32_t uvhi = ukv + 2 * ATB;
        const uint32_t uvlo = ukv + 3 * ATB;

        float sacc[8][4];
#pragma unroll
        for (int i = 0; i < 8; i++)
#pragma unroll
            for (int r = 0; r < 4; r++) sacc[i][r] = 0.f;

#pragma unroll
        for (int kk = 0; kk < 8; kk++) {
            uint32_t qh[4], ql[4];
            ldm_x4(qh, uQh + qoff + kk * 32);
            ldm_x4(ql, uQl + qoff + kk * 32);
#pragma unroll
            for (int njp = 0; njp < 4; njp++) {
                uint32_t kb[4];
                ldm_x4(kb, ukhi + njp * (16 * 272) + koff + kk * 32);
                mma16816(sacc[2 * njp],     qh, kb);
                mma16816(sacc[2 * njp + 1], qh, kb + 2);
                mma16816(sacc[2 * njp],     ql, kb);
                mma16816(sacc[2 * njp + 1], ql, kb + 2);
            }
#pragma unroll
            for (int njp = 0; njp < 4; njp++) {
                uint32_t kb[4];
                ldm_x4(kb, uklo + njp * (16 * 272) + koff + kk * 32);
                mma16816(sacc[2 * njp],     qh, kb);
                mma16816(sacc[2 * njp + 1], qh, kb + 2);
            }
        }

        const bool diag = (kt == qt);
        uint32_t ahi[4][4], alo[4][4];
#pragma unroll
        for (int nj = 0; nj < 8; nj++) {
            float p0 = __expf(sacc[nj][0] * cSCALE);
            float p1 = __expf(sacc[nj][1] * cSCALE);
            float p2 = __expf(sacc[nj][2] * cSCALE);
            float p3 = __expf(sacc[nj][3] * cSCALE);
            if (diag) {
                const int cbase = nj * 8 + 2 * t;
                const int rlo = wr + g, rhi = wr + 8 + g;
                if (cbase     > rlo) p0 = 0.f;
                if (cbase + 1 > rlo) p1 = 0.f;
                if (cbase     > rhi) p2 = 0.f;
                if (cbase + 1 > rhi) p3 = 0.f;
            }
            l0 += p0 + p1;
            l1 += p2 + p3;
            if (write_w) {
                float* wp = wout + ((size_t)(b * cNH + h) * cS + q0 + wr + g) * cS
                            + kt * 64 + nj * 8 + 2 * t;
                *(float2*)wp = make_float2(p0, p1);
                *(float2*)(wp + 8 * (size_t)cS) = make_float2(p2, p3);
            }
            float h0 = __bfloat162float(__float2bfloat16(p0));
            float h1 = __bfloat162float(__float2bfloat16(p1));
            float h2 = __bfloat162float(__float2bfloat16(p2));
            float h3 = __bfloat162float(__float2bfloat16(p3));
            const int kkB = nj >> 1;
            const int sub = (nj & 1) * 2;
            ahi[kkB][sub]     = pack_bf16(h0, h1);
            ahi[kkB][sub + 1] = pack_bf16(h2, h3);
            alo[kkB][sub]     = pack_bf16(p0 - h0, p1 - h1);
            alo[kkB][sub + 1] = pack_bf16(p2 - h2, p3 - h3);
        }

#pragma unroll
        for (int kk = 0; kk < 4; kk++) {
#pragma unroll
            for (int ndp = 0; ndp < 8; ndp++) {
                uint32_t vb[4];
                ldm_x4t(vb, uvhi + kk * (16 * 272) + ndp * 32 + voff);
                mma16816(oacc[2 * ndp],     ahi[kk], vb);
                mma16816(oacc[2 * ndp + 1], ahi[kk], vb + 2);
                mma16816(oacc[2 * ndp],     alo[kk], vb);
                mma16816(oacc[2 * ndp + 1], alo[kk], vb + 2);
            }
#pragma unroll
            for (int ndp = 0; ndp < 8; ndp++) {
                uint32_t vb[4];
                ldm_x4t(vb, uvlo + kk * (16 * 272) + ndp * 32 + voff);
                mma16816(oacc[2 * ndp],     ahi[kk], vb);
                mma16816(oacc[2 * ndp + 1], ahi[kk], vb + 2);
            }
        }
        __syncthreads();
    }

    l0 += __shfl_xor_sync(0xffffffffu, l0, 1);
    l0 += __shfl_xor_sync(0xffffffffu, l0, 2);
    l1 += __shfl_xor_sync(0xffffffffu, l1, 1);
    l1 += __shfl_xor_sync(0xffffffffu, l1, 2);
    const float inv0 = 1.f / l0;
    const float inv1 = 1.f / l1;

    if (write_w && t == 0) {
        lsum[(size_t)(b * cNH + h) * cS + q0 + wr + g]     = l0;
        lsum[(size_t)(b * cNH + h) * cS + q0 + wr + 8 + g] = l1;
    }

#pragma unroll
    for (int nd = 0; nd < 16; nd++) {
        const int col = nd * 8 + 2 * t;
        float* o0 = outp + ((size_t)(b * cS + q0 + wr + g) * cNH + h) * cHD + col;
        float* o1 = outp + ((size_t)(b * cS + q0 + wr + 8 + g) * cNH + h) * cHD + col;
        *(float2*)o0 = make_float2(tf32r(oacc[nd][0] * inv0),
                                   tf32r(oacc[nd][1] * inv0));
        *(float2*)o1 = make_float2(tf32r(oacc[nd][2] * inv1),
                                   tf32r(oacc[nd][3] * inv1));
    }
}

// ---------------------------------------------------------------------------
// Normalize weights rows by 1/l; zero the never-written upper triangle.
// ---------------------------------------------------------------------------
__global__ __launch_bounds__(256) void norm_weights_kernel(
    float* __restrict__ w, const float* __restrict__ lsum)
{
    const int row = blockIdx.x;
    const int q   = row & (cS - 1);
    const int valid = ((q >> 6) + 1) << 6;
    const float inv = 1.f / lsum[row];
    float* wr = w + (size_t)row * cS;
    const int tid = threadIdx.x;
#pragma unroll
    for (int i = 0; i < 2; i++) {
        int c = (tid + i * 256) * 4;
        if (c < valid) {
            float4 v = *(float4*)(wr + c);
            v.x *= inv; v.y *= inv; v.z *= inv; v.w *= inv;
            *(float4*)(wr + c) = v;
        } else {
            *(float4*)(wr + c) = make_float4(0.f, 0.f, 0.f, 0.f);
        }
    }
}

// ---------------------------------------------------------------------------
// Launch
// ---------------------------------------------------------------------------
extern "C" void kernel_launch(void* const* d_in, const int* in_sizes, int n_in,
                              void* d_out, int out_size)
{
    const float* hidden = (const float*)d_in[0];
    const float* cosp   = (const float*)d_in[1];
    const float* sinp   = (const float*)d_in[2];
    const float* wq  = (const float*)d_in[4];
    const float* wk  = (const float*)d_in[5];
    const float* wv  = (const float*)d_in[6];
    const float* wo  = (const float*)d_in[7];
    const float* qnw = (const float*)d_in[8];
    const float* knw = (const float*)d_in[9];

    float* out = (float*)d_out;
    const size_t n_attn = (size_t)cM * cHID;
    const size_t n_w    = (size_t)cB * cNH * cS * cS;
    const int write_w   = ((size_t)out_size >= n_attn + n_w) ? 1 : 0;
    float* weights = out + n_attn;

    float *pahf, *pqkv, *pa, *pwt, *pwot, *pl;
    cudaGetSymbolAddress((void**)&pahf, g_ahf);
    cudaGetSymbolAddress((void**)&pqkv, g_qkv);
    cudaGetSymbolAddress((void**)&pa,   g_att);
    cudaGetSymbolAddress((void**)&pwt,  g_wt);
    cudaGetSymbolAddress((void**)&pwot, g_wot);
    cudaGetSymbolAddress((void**)&pl,   g_l);
    __nv_bfloat16 *pqh, *pql, *pkh, *pklo, *pvh, *pvlo;
    cudaGetSymbolAddress((void**)&pqh,  g_q2hi);
    cudaGetSymbolAddress((void**)&pql,  g_q2lo);
    cudaGetSymbolAddress((void**)&pkh,  g_k2hi);
    cudaGetSymbolAddress((void**)&pklo, g_k2lo);
    cudaGetSymbolAddress((void**)&pvh,  g_v2hi);
    cudaGetSymbolAddress((void**)&pvlo, g_v2lo);

    static bool attr_done = false;
    if (!attr_done) {
        cudaFuncSetAttribute(gemm_tf32_kernel,
                             cudaFuncAttributeMaxDynamicSharedMemorySize, GEMM_SMEM);
        cudaFuncSetAttribute(attn_mma_kernel,
                             cudaFuncAttributeMaxDynamicSharedMemorySize, ATTN_SMEM);
        attr_done = true;
    }

    // --- prep: tf32-rounded A, transposed+rounded weights ---
    round_tf32_kernel<<<(cM * cHID / 4) / 256, 256>>>(hidden, pahf);
    cvt_wT_kernel<<<dim3(2048 / 32, 2048 / 32), dim3(32, 8)>>>(
        wq, pwt, cHID, 2048);
    cvt_wT_kernel<<<dim3(1024 / 32, 2048 / 32), dim3(32, 8)>>>(
        wk, pwt + (size_t)2048 * cHID, cHID, 1024);
    cvt_wT_kernel<<<dim3(1024 / 32, 2048 / 32), dim3(32, 8)>>>(
        wv, pwt + (size_t)3072 * cHID, cHID, 1024);
    cvt_wT_kernel<<<dim3(2048 / 32, 2048 / 32), dim3(32, 8)>>>(
        wo, pwot, cHID, 2048);

    // --- fused QKV projection (tf32) ---
    gemm_tf32_kernel<<<dim3(cNQKV / GBN, cM / GBM), 256, GEMM_SMEM>>>(
        pahf, pwt, pqkv, cM, cNQKV, cHID);

    // --- RMSNorm + RoPE + bf16 hi/lo split into head-major layout ---
    norm_rope_split_kernel<<<cM * 32, 128>>>(cosp, sinp, qnw, knw);

    // --- single-pass MMA attention ---
    attn_mma_kernel<<<dim3(cS / 64, cB * cNKV), 256, ATTN_SMEM>>>(
        pqh, pql, pkh, pklo, pvh, pvlo, weights, pl, pa, write_w);

    // --- normalize weights + zero upper triangle ---
    if (write_w)
        norm_weights_kernel<<<cB * cNH * cS, 256>>>(weights, pl);

    // --- output projection (tf32) ---
    gemm_tf32_kernel<<<dim3(cHID / GBN, cM / GBM), 256, GEMM_SMEM>>>(
        pa, pwot, out, cM, cHID, cHID);
}